// round 2
// baseline (speedup 1.0000x reference)
#include <cuda_runtime.h>
#include <cuda_bf16.h>
#include <cstdint>

// Problem constants
#define S_LEN 2048
#define D_DIM 1024
#define H_HEADS 16
#define DH_DIM 64
#define HID_DIM 4096

// ---------------- static scratch (no allocation allowed) ----------------
__device__ float g_WtS[D_DIM * D_DIM];
__device__ float g_WtC[D_DIM * D_DIM];
__device__ float g_P  [S_LEN * D_DIM];   // self-attn shared q=k=v projection
__device__ float g_Qc [S_LEN * D_DIM];   // cross-attn Q projection (from y1)
__device__ float g_Kc [S_LEN * D_DIM];   // cross-attn K=V projection (from encoder)
__device__ float g_AO [S_LEN * D_DIM];   // attention output (reused self/cross)
__device__ float g_y1 [S_LEN * D_DIM];
__device__ float g_y2 [S_LEN * D_DIM];
__device__ float g_Hd [S_LEN * HID_DIM];
__device__ float g_FF [S_LEN * D_DIM];

// ---------------- weight transpose: W[h][d][e] -> Wt[d][h*64+e] ----------------
__global__ void transpose_w_kernel(const float* __restrict__ W, float* __restrict__ Wt) {
    int idx = blockIdx.x * 256 + threadIdx.x;      // 0 .. 1024*1024-1
    int n = idx & (D_DIM - 1);
    int d = idx >> 10;
    int h = n >> 6;
    int e = n & 63;
    Wt[idx] = W[h * (D_DIM * DH_DIM) + d * DH_DIM + e];
}

// ---------------- tiled fp32 SGEMM: C = A@B + bias (+relu) ----------------
// A [M,K] rm, B [K,N] rm, bias [N]. BM=BN=64, BK=16, 256 threads, 4x4 microtile.
template<bool RELU>
__global__ void sgemm_bias_kernel(const float* __restrict__ A, const float* __restrict__ B,
                                  const float* __restrict__ bias, float* __restrict__ C,
                                  int M, int N, int K) {
    __shared__ float As[16][64];
    __shared__ float Bs[16][64];
    const int tid = threadIdx.x;
    const int tx = tid & 15;
    const int ty = tid >> 4;
    const int bm0 = blockIdx.y * 64;
    const int bn0 = blockIdx.x * 64;

    const int aRow  = tid >> 2;
    const int aCol4 = (tid & 3) * 4;
    const int bRow  = tid >> 4;
    const int bCol4 = (tid & 15) * 4;

    float acc[4][4];
    #pragma unroll
    for (int i = 0; i < 4; i++)
        #pragma unroll
        for (int j = 0; j < 4; j++) acc[i][j] = 0.f;

    for (int k0 = 0; k0 < K; k0 += 16) {
        float4 a4 = *(const float4*)&A[(size_t)(bm0 + aRow) * K + k0 + aCol4];
        float4 b4 = *(const float4*)&B[(size_t)(k0 + bRow) * N + bn0 + bCol4];
        __syncthreads();
        As[aCol4 + 0][aRow] = a4.x;
        As[aCol4 + 1][aRow] = a4.y;
        As[aCol4 + 2][aRow] = a4.z;
        As[aCol4 + 3][aRow] = a4.w;
        *(float4*)&Bs[bRow][bCol4] = b4;
        __syncthreads();
        #pragma unroll
        for (int k = 0; k < 16; k++) {
            float4 ra = *(const float4*)&As[k][ty * 4];
            float4 rb = *(const float4*)&Bs[k][tx * 4];
            float av[4] = {ra.x, ra.y, ra.z, ra.w};
            float bv[4] = {rb.x, rb.y, rb.z, rb.w};
            #pragma unroll
            for (int i = 0; i < 4; i++)
                #pragma unroll
                for (int j = 0; j < 4; j++)
                    acc[i][j] += av[i] * bv[j];
        }
    }

    #pragma unroll
    for (int i = 0; i < 4; i++) {
        int row = bm0 + ty * 4 + i;
        float4 o;
        float v0 = acc[i][0] + bias[bn0 + tx * 4 + 0];
        float v1 = acc[i][1] + bias[bn0 + tx * 4 + 1];
        float v2 = acc[i][2] + bias[bn0 + tx * 4 + 2];
        float v3 = acc[i][3] + bias[bn0 + tx * 4 + 3];
        if (RELU) {
            v0 = fmaxf(v0, 0.f); v1 = fmaxf(v1, 0.f);
            v2 = fmaxf(v2, 0.f); v3 = fmaxf(v3, 0.f);
        }
        o.x = v0; o.y = v1; o.z = v2; o.w = v3;
        *(float4*)&C[(size_t)row * N + bn0 + tx * 4] = o;
    }
}

// ---------------- flash-style attention (K == V) ----------------
// grid: (S/32, H). block: 256 threads = 8 warps, warp handles 4 query rows.
// Q, KV, Out in [S, D] layout; head h occupies columns [h*64, h*64+64).
#define AT_TQ 32
#define AT_TK 64
#define KPAD 67   // 67 mod 32 = 3, coprime with 32 -> conflict-free column reads

__global__ void attn_kernel(const float* __restrict__ Q, const float* __restrict__ KV,
                            float* __restrict__ Out, int causal) {
    __shared__ float KshT[64][KPAD];       // [d][t_local]
    __shared__ float Qsh[AT_TQ][64];       // [r][d]
    __shared__ float psh[8][4][AT_TK];     // per-warp p staging

    const int h   = blockIdx.y;
    const int q0  = blockIdx.x * AT_TQ;
    const int tid = threadIdx.x;
    const int warp = tid >> 5;
    const int lane = tid & 31;

    // load Q tile
    for (int i = tid; i < AT_TQ * 64; i += 256) {
        int r = i >> 6, d = i & 63;
        Qsh[r][d] = Q[(size_t)(q0 + r) * D_DIM + h * 64 + d];
    }

    float m[4], l[4], o[4][2];
    #pragma unroll
    for (int r = 0; r < 4; r++) { m[r] = -1e30f; l[r] = 0.f; o[r][0] = 0.f; o[r][1] = 0.f; }

    const int ntiles = causal ? ((q0 + AT_TQ - 1) / AT_TK + 1) : (S_LEN / AT_TK);
    const float scale = 0.125f;   // 1/sqrt(64)

    for (int kt = 0; kt < ntiles; kt++) {
        const int t0 = kt * AT_TK;
        __syncthreads();   // protect KshT/psh from previous iteration (and Qsh on iter 0)
        for (int i = tid; i < AT_TK * 64; i += 256) {
            int tl = i >> 6, d = i & 63;
            KshT[d][tl] = KV[(size_t)(t0 + tl) * D_DIM + h * 64 + d];
        }
        __syncthreads();

        // ---- scores: s[r][kk], lane's keys are (lane) and (lane+32) ----
        float s[4][2];
        #pragma unroll
        for (int r = 0; r < 4; r++) { s[r][0] = 0.f; s[r][1] = 0.f; }

        #pragma unroll
        for (int dc = 0; dc < 64; dc += 8) {
            float kv0[8], kv1[8];
            #pragma unroll
            for (int d = 0; d < 8; d++) {
                kv0[d] = KshT[dc + d][lane];
                kv1[d] = KshT[dc + d][lane + 32];
            }
            #pragma unroll
            for (int r = 0; r < 4; r++) {
                #pragma unroll
                for (int d = 0; d < 8; d++) {
                    float qv = Qsh[warp * 4 + r][dc + d];
                    s[r][0] += qv * kv0[d];
                    s[r][1] += qv * kv1[d];
                }
            }
        }

        // ---- online softmax per row ----
        #pragma unroll
        for (int r = 0; r < 4; r++) {
            const int qrow = q0 + warp * 4 + r;
            float s0 = s[r][0] * scale;
            float s1 = s[r][1] * scale;
            if (causal) {
                if (t0 + lane      > qrow) s0 = -1e9f;
                if (t0 + lane + 32 > qrow) s1 = -1e9f;
            }
            float mt = fmaxf(s0, s1);
            #pragma unroll
            for (int off = 16; off > 0; off >>= 1)
                mt = fmaxf(mt, __shfl_xor_sync(0xffffffffu, mt, off));
            float mn    = fmaxf(m[r], mt);
            float alpha = __expf(m[r] - mn);
            float p0 = __expf(s0 - mn);
            float p1 = __expf(s1 - mn);
            float ls = p0 + p1;
            #pragma unroll
            for (int off = 16; off > 0; off >>= 1)
                ls += __shfl_xor_sync(0xffffffffu, ls, off);
            l[r] = l[r] * alpha + ls;
            m[r] = mn;
            o[r][0] *= alpha;
            o[r][1] *= alpha;
            psh[warp][r][lane]      = p0;
            psh[warp][r][lane + 32] = p1;
        }
        __syncwarp();

        // ---- PV accumulate (V == K). Lane owns dims lane, lane+32. ----
        #pragma unroll 4
        for (int j = 0; j < AT_TK; j++) {
            float v0 = KshT[lane][j];
            float v1 = KshT[lane + 32][j];
            #pragma unroll
            for (int r = 0; r < 4; r++) {
                float p = psh[warp][r][j];
                o[r][0] += p * v0;
                o[r][1] += p * v1;
            }
        }
    }

    #pragma unroll
    for (int r = 0; r < 4; r++) {
        const int qrow = q0 + warp * 4 + r;
        float inv = 1.f / l[r];
        Out[(size_t)qrow * D_DIM + h * 64 + lane]      = o[r][0] * inv;
        Out[(size_t)qrow * D_DIM + h * 64 + lane + 32] = o[r][1] * inv;
    }
}

// ---------------- fused residual add + LayerNorm ----------------
// out[row] = LN(A[row] + Bv[row]) * g + beta ; one block per row, 256 threads.
__device__ __forceinline__ float warpReduceSum(float v) {
    #pragma unroll
    for (int off = 16; off > 0; off >>= 1)
        v += __shfl_xor_sync(0xffffffffu, v, off);
    return v;
}

__device__ __forceinline__ float blockReduceSum(float v, float* sh) {
    int lane = threadIdx.x & 31, w = threadIdx.x >> 5;
    __syncthreads();
    v = warpReduceSum(v);
    if (lane == 0) sh[w] = v;
    __syncthreads();
    if (w == 0) {
        float t = (lane < 8) ? sh[lane] : 0.f;
        t = warpReduceSum(t);
        if (lane == 0) sh[0] = t;
    }
    __syncthreads();
    return sh[0];
}

__global__ void add_ln_kernel(const float* __restrict__ A, const float* __restrict__ Bv,
                              const float* __restrict__ g, const float* __restrict__ beta,
                              float* __restrict__ out) {
    __shared__ float red[8];
    const int row = blockIdx.x;
    const int tid = threadIdx.x;
    float x[4];
    float s = 0.f;
    #pragma unroll
    for (int i = 0; i < 4; i++) {
        int c = tid + i * 256;
        x[i] = A[(size_t)row * D_DIM + c] + Bv[(size_t)row * D_DIM + c];
        s += x[i];
    }
    s = blockReduceSum(s, red);
    const float mu = s * (1.f / D_DIM);
    float v = 0.f;
    #pragma unroll
    for (int i = 0; i < 4; i++) {
        float d = x[i] - mu;
        v += d * d;
    }
    v = blockReduceSum(v, red);
    const float rstd = rsqrtf(v * (1.f / D_DIM) + 1e-5f);
    #pragma unroll
    for (int i = 0; i < 4; i++) {
        int c = tid + i * 256;
        out[(size_t)row * D_DIM + c] = (x[i] - mu) * rstd * g[c] + beta[c];
    }
}

// ---------------- launch ----------------
extern "C" void kernel_launch(void* const* d_in, const int* in_sizes, int n_in,
                              void* d_out, int out_size) {
    const float* y    = (const float*)d_in[0];
    const float* enc  = (const float*)d_in[1];
    const float* WqS  = (const float*)d_in[2];
    const float* bqS  = (const float*)d_in[3];
    const float* WqC  = (const float*)d_in[4];
    const float* bqC  = (const float*)d_in[5];
    const float* g1   = (const float*)d_in[6];
    const float* be1  = (const float*)d_in[7];
    const float* g2   = (const float*)d_in[8];
    const float* be2  = (const float*)d_in[9];
    const float* g3   = (const float*)d_in[10];
    const float* be3  = (const float*)d_in[11];
    const float* w1   = (const float*)d_in[12];
    const float* b1   = (const float*)d_in[13];
    const float* w2   = (const float*)d_in[14];
    const float* b2   = (const float*)d_in[15];
    float* outp = (float*)d_out;

    float *WtS, *WtC, *P, *Qc, *Kc, *AO, *y1, *y2, *Hd, *FF;
    cudaGetSymbolAddress((void**)&WtS, g_WtS);
    cudaGetSymbolAddress((void**)&WtC, g_WtC);
    cudaGetSymbolAddress((void**)&P,   g_P);
    cudaGetSymbolAddress((void**)&Qc,  g_Qc);
    cudaGetSymbolAddress((void**)&Kc,  g_Kc);
    cudaGetSymbolAddress((void**)&AO,  g_AO);
    cudaGetSymbolAddress((void**)&y1,  g_y1);
    cudaGetSymbolAddress((void**)&y2,  g_y2);
    cudaGetSymbolAddress((void**)&Hd,  g_Hd);
    cudaGetSymbolAddress((void**)&FF,  g_FF);

    // 1. weight transposes
    transpose_w_kernel<<<(D_DIM * D_DIM) / 256, 256>>>(WqS, WtS);
    transpose_w_kernel<<<(D_DIM * D_DIM) / 256, 256>>>(WqC, WtC);

    dim3 gemm_blk(256);

    // 2. self-attn shared projection: P = y @ WtS + bqS   [2048,1024]
    sgemm_bias_kernel<false><<<dim3(D_DIM / 64, S_LEN / 64), gemm_blk>>>(y, WtS, bqS, P, S_LEN, D_DIM, D_DIM);

    // 3. causal self-attention (q=k=v=P)
    attn_kernel<<<dim3(S_LEN / AT_TQ, H_HEADS), 256>>>(P, P, AO, 1);

    // 4. y1 = LN(y + AO)
    add_ln_kernel<<<S_LEN, 256>>>(y, AO, g1, be1, y1);

    // 5. cross Q projection: Qc = y1 @ WtC + bqC
    sgemm_bias_kernel<false><<<dim3(D_DIM / 64, S_LEN / 64), gemm_blk>>>(y1, WtC, bqC, Qc, S_LEN, D_DIM, D_DIM);

    // 6. cross K=V projection: Kc = enc @ WtC + bqC
    sgemm_bias_kernel<false><<<dim3(D_DIM / 64, S_LEN / 64), gemm_blk>>>(enc, WtC, bqC, Kc, S_LEN, D_DIM, D_DIM);

    // 7. cross attention (non-causal, k=v)
    attn_kernel<<<dim3(S_LEN / AT_TQ, H_HEADS), 256>>>(Qc, Kc, AO, 0);

    // 8. y2 = LN(y1 + AO)
    add_ln_kernel<<<S_LEN, 256>>>(y1, AO, g2, be2, y2);

    // 9. Hd = relu(y2 @ w1 + b1)   [2048,4096]
    sgemm_bias_kernel<true><<<dim3(HID_DIM / 64, S_LEN / 64), gemm_blk>>>(y2, w1, b1, Hd, S_LEN, HID_DIM, D_DIM);

    // 10. FF = Hd @ w2 + b2        [2048,1024]
    sgemm_bias_kernel<false><<<dim3(D_DIM / 64, S_LEN / 64), gemm_blk>>>(Hd, w2, b2, FF, S_LEN, D_DIM, HID_DIM);

    // 11. out = LN(y2 + FF)
    add_ln_kernel<<<S_LEN, 256>>>(y2, FF, g3, be3, outp);
}

// round 7
// speedup vs baseline: 1.4715x; 1.4715x over previous
#include <cuda_runtime.h>
#include <cuda_bf16.h>
#include <cstdint>

#define S_LEN 2048
#define D_DIM 1024
#define H_HEADS 16
#define DH_DIM 64
#define HID_DIM 4096

typedef __nv_bfloat16 bf16;

// ---------------- static scratch ----------------
__device__ float g_P  [S_LEN * D_DIM];
__device__ float g_Qc [S_LEN * D_DIM];
__device__ float g_Kc [S_LEN * D_DIM];
__device__ float g_AO [S_LEN * D_DIM];
__device__ float g_y1 [S_LEN * D_DIM];
__device__ float g_y2 [S_LEN * D_DIM];
__device__ float g_Hd [S_LEN * HID_DIM];
__device__ float g_FF [S_LEN * D_DIM];

// bf16 hi/lo weight copies, K-major [N][K]
__device__ bf16 g_BtS_hi[D_DIM * D_DIM];
__device__ bf16 g_BtS_lo[D_DIM * D_DIM];
__device__ bf16 g_BtC_hi[D_DIM * D_DIM];
__device__ bf16 g_BtC_lo[D_DIM * D_DIM];
__device__ bf16 g_Bt1_hi[HID_DIM * D_DIM];
__device__ bf16 g_Bt1_lo[HID_DIM * D_DIM];
__device__ bf16 g_Bt2_hi[D_DIM * HID_DIM];
__device__ bf16 g_Bt2_lo[D_DIM * HID_DIM];
// activation hi/lo (reused; sized for largest = Hd)
__device__ bf16 g_Ahi[S_LEN * HID_DIM];
__device__ bf16 g_Alo[S_LEN * HID_DIM];

// ---------------- helpers ----------------
__device__ __forceinline__ uint32_t smem_u32(const void* p) {
    uint32_t a;
    asm("{ .reg .u64 t; cvta.to.shared.u64 t, %1; cvt.u32.u64 %0, t; }" : "=r"(a) : "l"(p));
    return a;
}
__device__ __forceinline__ uint32_t pk2(bf16 a, bf16 b) {
    return (uint32_t)__bfloat16_as_ushort(a) | ((uint32_t)__bfloat16_as_ushort(b) << 16);
}
__device__ __forceinline__ void ldsm4(uint32_t r[4], uint32_t addr) {
    asm volatile("ldmatrix.sync.aligned.m8n8.x4.shared.b16 {%0,%1,%2,%3}, [%4];"
        : "=r"(r[0]), "=r"(r[1]), "=r"(r[2]), "=r"(r[3]) : "r"(addr));
}
__device__ __forceinline__ void ldsm2(uint32_t r[2], uint32_t addr) {
    asm volatile("ldmatrix.sync.aligned.m8n8.x2.shared.b16 {%0,%1}, [%2];"
        : "=r"(r[0]), "=r"(r[1]) : "r"(addr));
}
__device__ __forceinline__ void mma_bf16(float d[4], const uint32_t a[4], const uint32_t b[2]) {
    asm volatile(
        "mma.sync.aligned.m16n8k16.row.col.f32.bf16.bf16.f32 "
        "{%0,%1,%2,%3}, {%4,%5,%6,%7}, {%8,%9}, {%0,%1,%2,%3};"
        : "+f"(d[0]), "+f"(d[1]), "+f"(d[2]), "+f"(d[3])
        : "r"(a[0]), "r"(a[1]), "r"(a[2]), "r"(a[3]), "r"(b[0]), "r"(b[1]));
}

// ---------------- split-bf16 mma.sync GEMM: C = A@B^T + bias (+relu) ----------------
// A hi/lo [M,K] K-major; B hi/lo [N,K] K-major. Tile 128x128x32, 256 thr (8 warps 2x4).
#define SMSTR 40   // smem row stride in halves (32 + 8 pad) -> conflict-free ldmatrix

template<bool RELU>
__global__ void __launch_bounds__(256, 1) mm_gemm(
    const bf16* __restrict__ Ahi, const bf16* __restrict__ Alo,
    const bf16* __restrict__ Bhi, const bf16* __restrict__ Blo,
    const float* __restrict__ bias, float* __restrict__ C,
    int N, int K)
{
    __shared__ bf16 As_hi[128][SMSTR];
    __shared__ bf16 As_lo[128][SMSTR];
    __shared__ bf16 Bs_hi[128][SMSTR];
    __shared__ bf16 Bs_lo[128][SMSTR];

    const int tid  = threadIdx.x;
    const int warp = tid >> 5;
    const int lane = tid & 31;
    const int bm0  = blockIdx.y * 128;
    const int bn0  = blockIdx.x * 128;
    const int wm   = (warp & 1) * 64;   // warp row offset in tile
    const int wn   = (warp >> 1) * 32;  // warp col offset in tile

    float acc[4][4][4];
    #pragma unroll
    for (int mt = 0; mt < 4; mt++)
        #pragma unroll
        for (int nt = 0; nt < 4; nt++)
            #pragma unroll
            for (int i = 0; i < 4; i++) acc[mt][nt][i] = 0.f;

    // precompute ldmatrix lane address components
    const int a_r = lane & 15;             // row within 16-row tile
    const int a_c = (lane >> 4) * 8;       // col half (0 or 8)
    const int b_r = lane & 7;
    const int b_c = ((lane >> 3) & 1) * 8;

    for (int k0 = 0; k0 < K; k0 += 32) {
        __syncthreads();
        #pragma unroll
        for (int t = 0; t < 2; t++) {
            int i = tid + t * 256;        // 0..511
            int row = i >> 2, seg = (i & 3) * 8;
            size_t ga = (size_t)(bm0 + row) * K + k0 + seg;
            size_t gb = (size_t)(bn0 + row) * K + k0 + seg;
            *(uint4*)&As_hi[row][seg] = *(const uint4*)&Ahi[ga];
            *(uint4*)&As_lo[row][seg] = *(const uint4*)&Alo[ga];
            *(uint4*)&Bs_hi[row][seg] = *(const uint4*)&Bhi[gb];
            *(uint4*)&Bs_lo[row][seg] = *(const uint4*)&Blo[gb];
        }
        __syncthreads();

        #pragma unroll
        for (int ks = 0; ks < 2; ks++) {
            uint32_t ah[4][4], al[4][4], bh[4][2], bl[4][2];
            #pragma unroll
            for (int mt = 0; mt < 4; mt++) {
                int r = wm + mt * 16 + a_r;
                int c = ks * 16 + a_c;
                ldsm4(ah[mt], smem_u32(&As_hi[r][c]));
                ldsm4(al[mt], smem_u32(&As_lo[r][c]));
            }
            #pragma unroll
            for (int nt = 0; nt < 4; nt++) {
                int r = wn + nt * 8 + b_r;
                int c = ks * 16 + b_c;
                ldsm2(bh[nt], smem_u32(&Bs_hi[r][c]));
                ldsm2(bl[nt], smem_u32(&Bs_lo[r][c]));
            }
            #pragma unroll
            for (int mt = 0; mt < 4; mt++)
                #pragma unroll
                for (int nt = 0; nt < 4; nt++) {
                    mma_bf16(acc[mt][nt], ah[mt], bh[nt]);
                    mma_bf16(acc[mt][nt], ah[mt], bl[nt]);
                    mma_bf16(acc[mt][nt], al[mt], bh[nt]);
                }
        }
    }

    // epilogue: direct stores, fragment layout (r=lane>>2, c=(lane&3)*2)
    #pragma unroll
    for (int mt = 0; mt < 4; mt++) {
        #pragma unroll
        for (int nt = 0; nt < 4; nt++) {
            int row = bm0 + wm + mt * 16 + (lane >> 2);
            int col = bn0 + wn + nt * 8 + (lane & 3) * 2;
            float bv0 = bias[col], bv1 = bias[col + 1];
            float v0 = acc[mt][nt][0] + bv0;
            float v1 = acc[mt][nt][1] + bv1;
            float v2 = acc[mt][nt][2] + bv0;
            float v3 = acc[mt][nt][3] + bv1;
            if (RELU) {
                v0 = fmaxf(v0, 0.f); v1 = fmaxf(v1, 0.f);
                v2 = fmaxf(v2, 0.f); v3 = fmaxf(v3, 0.f);
            }
            *(float2*)&C[(size_t)row * N + col]       = make_float2(v0, v1);
            *(float2*)&C[(size_t)(row + 8) * N + col] = make_float2(v2, v3);
        }
    }
}

// ---------------- activation fp32 -> bf16 hi/lo split ----------------
__global__ void cvt_act(const float4* __restrict__ x, uint2* __restrict__ hi,
                        uint2* __restrict__ lo, int n4) {
    int i = blockIdx.x * 256 + threadIdx.x;
    if (i >= n4) return;
    float4 v = x[i];
    bf16 h0 = __float2bfloat16(v.x), h1 = __float2bfloat16(v.y);
    bf16 h2 = __float2bfloat16(v.z), h3 = __float2bfloat16(v.w);
    bf16 l0 = __float2bfloat16(v.x - __bfloat162float(h0));
    bf16 l1 = __float2bfloat16(v.y - __bfloat162float(h1));
    bf16 l2 = __float2bfloat16(v.z - __bfloat162float(h2));
    bf16 l3 = __float2bfloat16(v.w - __bfloat162float(h3));
    hi[i] = make_uint2(pk2(h0, h1), pk2(h2, h3));
    lo[i] = make_uint2(pk2(l0, l1), pk2(l2, l3));
}

// ---------------- proj weight: W[h][k][e] -> Bt[n=h*64+e][k] hi/lo ----------------
__global__ void prep_projW(const float* __restrict__ W, bf16* __restrict__ hi,
                           bf16* __restrict__ lo) {
    int idx = blockIdx.x * 256 + threadIdx.x;     // n*1024 + k
    int k = idx & 1023, n = idx >> 10;
    int h = n >> 6, e = n & 63;
    float v = W[(h << 16) + (k << 6) + e];
    bf16 hv = __float2bfloat16(v);
    hi[idx] = hv;
    lo[idx] = __float2bfloat16(v - __bfloat162float(hv));
}

// ---------------- tiled transpose+convert: in[R][C] -> out[C][R] hi/lo ----------------
__global__ void prep_T(const float* __restrict__ in, bf16* __restrict__ hi,
                       bf16* __restrict__ lo, int R, int C) {
    __shared__ float t[32][33];
    int bx = blockIdx.x * 32, by = blockIdx.y * 32;
    int tx = threadIdx.x, ty = threadIdx.y;   // 32x8
    #pragma unroll
    for (int i = 0; i < 32; i += 8)
        t[ty + i][tx] = in[(size_t)(by + ty + i) * C + bx + tx];
    __syncthreads();
    #pragma unroll
    for (int i = 0; i < 32; i += 8) {
        float v = t[tx][ty + i];
        bf16 hv = __float2bfloat16(v);
        size_t o = (size_t)(bx + ty + i) * R + by + tx;
        hi[o] = hv;
        lo[o] = __float2bfloat16(v - __bfloat162float(hv));
    }
}

// ---------------- flash-style attention (K == V), fp32 ----------------
#define AT_TQ 32
#define AT_TK 64
#define KPAD 67

__global__ void attn_kernel(const float* __restrict__ Q, const float* __restrict__ KV,
                            float* __restrict__ Out, int causal) {
    __shared__ float KshT[64][KPAD];
    __shared__ float Qsh[AT_TQ][64];
    __shared__ float psh[8][4][AT_TK];

    const int h = blockIdx.y;
    const int q0 = blockIdx.x * AT_TQ;
    const int tid = threadIdx.x;
    const int warp = tid >> 5;
    const int lane = tid & 31;

    for (int i = tid; i < AT_TQ * 64; i += 256) {
        int r = i >> 6, d = i & 63;
        Qsh[r][d] = Q[(size_t)(q0 + r) * D_DIM + h * 64 + d];
    }

    float m[4], l[4], o[4][2];
    #pragma unroll
    for (int r = 0; r < 4; r++) { m[r] = -1e30f; l[r] = 0.f; o[r][0] = 0.f; o[r][1] = 0.f; }

    const int ntiles = causal ? ((q0 + AT_TQ - 1) / AT_TK + 1) : (S_LEN / AT_TK);
    const float scale = 0.125f;

    for (int kt = 0; kt < ntiles; kt++) {
        const int t0 = kt * AT_TK;
        __syncthreads();
        for (int i = tid; i < AT_TK * 64; i += 256) {
            int tl = i >> 6, d = i & 63;
            KshT[d][tl] = KV[(size_t)(t0 + tl) * D_DIM + h * 64 + d];
        }
        __syncthreads();

        float s[4][2];
        #pragma unroll
        for (int r = 0; r < 4; r++) { s[r][0] = 0.f; s[r][1] = 0.f; }

        #pragma unroll
        for (int dc = 0; dc < 64; dc += 8) {
            float kv0[8], kv1[8];
            #pragma unroll
            for (int d = 0; d < 8; d++) {
                kv0[d] = KshT[dc + d][lane];
                kv1[d] = KshT[dc + d][lane + 32];
            }
            #pragma unroll
            for (int r = 0; r < 4; r++) {
                #pragma unroll
                for (int d = 0; d < 8; d++) {
                    float qv = Qsh[warp * 4 + r][dc + d];
                    s[r][0] += qv * kv0[d];
                    s[r][1] += qv * kv1[d];
                }
            }
        }

        #pragma unroll
        for (int r = 0; r < 4; r++) {
            const int qrow = q0 + warp * 4 + r;
            float s0 = s[r][0] * scale;
            float s1 = s[r][1] * scale;
            if (causal) {
                if (t0 + lane      > qrow) s0 = -1e9f;
                if (t0 + lane + 32 > qrow) s1 = -1e9f;
            }
            float mt = fmaxf(s0, s1);
            #pragma unroll
            for (int off = 16; off > 0; off >>= 1)
                mt = fmaxf(mt, __shfl_xor_sync(0xffffffffu, mt, off));
            float mn = fmaxf(m[r], mt);
            float alpha = __expf(m[r] - mn);
            float p0 = __expf(s0 - mn);
            float p1 = __expf(s1 - mn);
            float ls = p0 + p1;
            #pragma unroll
            for (int off = 16; off > 0; off >>= 1)
                ls += __shfl_xor_sync(0xffffffffu, ls, off);
            l[r] = l[r] * alpha + ls;
            m[r] = mn;
            o[r][0] *= alpha;
            o[r][1] *= alpha;
            psh[warp][r][lane]      = p0;
            psh[warp][r][lane + 32] = p1;
        }
        __syncwarp();

        #pragma unroll 4
        for (int j = 0; j < AT_TK; j++) {
            float v0 = KshT[lane][j];
            float v1 = KshT[lane + 32][j];
            #pragma unroll
            for (int r = 0; r < 4; r++) {
                float p = psh[warp][r][j];
                o[r][0] += p * v0;
                o[r][1] += p * v1;
            }
        }
    }

    #pragma unroll
    for (int r = 0; r < 4; r++) {
        const int qrow = q0 + warp * 4 + r;
        float inv = 1.f / l[r];
        Out[(size_t)qrow * D_DIM + h * 64 + lane]      = o[r][0] * inv;
        Out[(size_t)qrow * D_DIM + h * 64 + lane + 32] = o[r][1] * inv;
    }
}

// ---------------- fused residual add + LayerNorm ----------------
__device__ __forceinline__ float warpReduceSum(float v) {
    #pragma unroll
    for (int off = 16; off > 0; off >>= 1)
        v += __shfl_xor_sync(0xffffffffu, v, off);
    return v;
}
__device__ __forceinline__ float blockReduceSum(float v, float* sh) {
    int lane = threadIdx.x & 31, w = threadIdx.x >> 5;
    __syncthreads();
    v = warpReduceSum(v);
    if (lane == 0) sh[w] = v;
    __syncthreads();
    if (w == 0) {
        float t = (lane < 8) ? sh[lane] : 0.f;
        t = warpReduceSum(t);
        if (lane == 0) sh[0] = t;
    }
    __syncthreads();
    return sh[0];
}
__global__ void add_ln_kernel(const float* __restrict__ A, const float* __restrict__ Bv,
                              const float* __restrict__ g, const float* __restrict__ beta,
                              float* __restrict__ out) {
    __shared__ float red[8];
    const int row = blockIdx.x;
    const int tid = threadIdx.x;
    float x[4];
    float s = 0.f;
    #pragma unroll
    for (int i = 0; i < 4; i++) {
        int c = tid + i * 256;
        x[i] = A[(size_t)row * D_DIM + c] + Bv[(size_t)row * D_DIM + c];
        s += x[i];
    }
    s = blockReduceSum(s, red);
    const float mu = s * (1.f / D_DIM);
    float v = 0.f;
    #pragma unroll
    for (int i = 0; i < 4; i++) { float d = x[i] - mu; v += d * d; }
    v = blockReduceSum(v, red);
    const float rstd = rsqrtf(v * (1.f / D_DIM) + 1e-5f);
    #pragma unroll
    for (int i = 0; i < 4; i++) {
        int c = tid + i * 256;
        out[(size_t)row * D_DIM + c] = (x[i] - mu) * rstd * g[c] + beta[c];
    }
}

// ---------------- launch ----------------
extern "C" void kernel_launch(void* const* d_in, const int* in_sizes, int n_in,
                              void* d_out, int out_size) {
    const float* y   = (const float*)d_in[0];
    const float* enc = (const float*)d_in[1];
    const float* WqS = (const float*)d_in[2];
    const float* bqS = (const float*)d_in[3];
    const float* WqC = (const float*)d_in[4];
    const float* bqC = (const float*)d_in[5];
    const float* g1  = (const float*)d_in[6];
    const float* be1 = (const float*)d_in[7];
    const float* g2  = (const float*)d_in[8];
    const float* be2 = (const float*)d_in[9];
    const float* g3  = (const float*)d_in[10];
    const float* be3 = (const float*)d_in[11];
    const float* w1  = (const float*)d_in[12];
    const float* b1  = (const float*)d_in[13];
    const float* w2  = (const float*)d_in[14];
    const float* b2  = (const float*)d_in[15];
    float* outp = (float*)d_out;

    float *P, *Qc, *Kc, *AO, *y1, *y2, *Hd, *FF;
    bf16 *BtS_hi, *BtS_lo, *BtC_hi, *BtC_lo, *Bt1_hi, *Bt1_lo, *Bt2_hi, *Bt2_lo, *Ahi, *Alo;
    cudaGetSymbolAddress((void**)&P,  g_P);
    cudaGetSymbolAddress((void**)&Qc, g_Qc);
    cudaGetSymbolAddress((void**)&Kc, g_Kc);
    cudaGetSymbolAddress((void**)&AO, g_AO);
    cudaGetSymbolAddress((void**)&y1, g_y1);
    cudaGetSymbolAddress((void**)&y2, g_y2);
    cudaGetSymbolAddress((void**)&Hd, g_Hd);
    cudaGetSymbolAddress((void**)&FF, g_FF);
    cudaGetSymbolAddress((void**)&BtS_hi, g_BtS_hi);
    cudaGetSymbolAddress((void**)&BtS_lo, g_BtS_lo);
    cudaGetSymbolAddress((void**)&BtC_hi, g_BtC_hi);
    cudaGetSymbolAddress((void**)&BtC_lo, g_BtC_lo);
    cudaGetSymbolAddress((void**)&Bt1_hi, g_Bt1_hi);
    cudaGetSymbolAddress((void**)&Bt1_lo, g_Bt1_lo);
    cudaGetSymbolAddress((void**)&Bt2_hi, g_Bt2_hi);
    cudaGetSymbolAddress((void**)&Bt2_lo, g_Bt2_lo);
    cudaGetSymbolAddress((void**)&Ahi, g_Ahi);
    cudaGetSymbolAddress((void**)&Alo, g_Alo);

    // weight prep (hi/lo split, K-major)
    prep_projW<<<(D_DIM * D_DIM) / 256, 256>>>(WqS, BtS_hi, BtS_lo);
    prep_projW<<<(D_DIM * D_DIM) / 256, 256>>>(WqC, BtC_hi, BtC_lo);
    prep_T<<<dim3(HID_DIM / 32, D_DIM / 32), dim3(32, 8)>>>(w1, Bt1_hi, Bt1_lo, D_DIM, HID_DIM);
    prep_T<<<dim3(D_DIM / 32, HID_DIM / 32), dim3(32, 8)>>>(w2, Bt2_hi, Bt2_lo, HID_DIM, D_DIM);

    const int N_SD = S_LEN * D_DIM;     // 2M
    const int N_SH = S_LEN * HID_DIM;   // 8M

    // P = y @ WtS + bqS
    cvt_act<<<N_SD / 4 / 256, 256>>>((const float4*)y, (uint2*)Ahi, (uint2*)Alo, N_SD / 4);
    mm_gemm<false><<<dim3(D_DIM / 128, S_LEN / 128), 256>>>(
        Ahi, Alo, BtS_hi, BtS_lo, bqS, P, D_DIM, D_DIM);

    // self attention (q=k=v=P), causal
    attn_kernel<<<dim3(S_LEN / AT_TQ, H_HEADS), 256>>>(P, P, AO, 1);
    add_ln_kernel<<<S_LEN, 256>>>(y, AO, g1, be1, y1);

    // Qc = y1 @ WtC + bqC
    cvt_act<<<N_SD / 4 / 256, 256>>>((const float4*)y1, (uint2*)Ahi, (uint2*)Alo, N_SD / 4);
    mm_gemm<false><<<dim3(D_DIM / 128, S_LEN / 128), 256>>>(
        Ahi, Alo, BtC_hi, BtC_lo, bqC, Qc, D_DIM, D_DIM);

    // Kc = enc @ WtC + bqC
    cvt_act<<<N_SD / 4 / 256, 256>>>((const float4*)enc, (uint2*)Ahi, (uint2*)Alo, N_SD / 4);
    mm_gemm<false><<<dim3(D_DIM / 128, S_LEN / 128), 256>>>(
        Ahi, Alo, BtC_hi, BtC_lo, bqC, Kc, D_DIM, D_DIM);

    // cross attention (k=v), non-causal
    attn_kernel<<<dim3(S_LEN / AT_TQ, H_HEADS), 256>>>(Qc, Kc, AO, 0);
    add_ln_kernel<<<S_LEN, 256>>>(y1, AO, g2, be2, y2);

    // Hd = relu(y2 @ w1 + b1)
    cvt_act<<<N_SD / 4 / 256, 256>>>((const float4*)y2, (uint2*)Ahi, (uint2*)Alo, N_SD / 4);
    mm_gemm<true><<<dim3(HID_DIM / 128, S_LEN / 128), 256>>>(
        Ahi, Alo, Bt1_hi, Bt1_lo, b1, Hd, HID_DIM, D_DIM);

    // FF = Hd @ w2 + b2
    cvt_act<<<N_SH / 4 / 256, 256>>>((const float4*)Hd, (uint2*)Ahi, (uint2*)Alo, N_SH / 4);
    mm_gemm<false><<<dim3(D_DIM / 128, S_LEN / 128), 256>>>(
        Ahi, Alo, Bt2_hi, Bt2_lo, b2, FF, D_DIM, HID_DIM);

    add_ln_kernel<<<S_LEN, 256>>>(y2, FF, g3, be3, outp);
}

// round 8
// speedup vs baseline: 2.3839x; 1.6200x over previous
#include <cuda_runtime.h>
#include <cuda_bf16.h>
#include <cstdint>

#define S_LEN 2048
#define D_DIM 1024
#define H_HEADS 16
#define DH_DIM 64
#define HID_DIM 4096

typedef __nv_bfloat16 bf16;

// ---------------- static scratch ----------------
__device__ float g_AO [S_LEN * D_DIM];
__device__ float g_y1 [S_LEN * D_DIM];
__device__ float g_y2 [S_LEN * D_DIM];
__device__ float g_FF [S_LEN * D_DIM];

// hi/lo bf16 activations
__device__ bf16 g_Phi [S_LEN * D_DIM];
__device__ bf16 g_Plo [S_LEN * D_DIM];
__device__ bf16 g_Qchi[S_LEN * D_DIM];
__device__ bf16 g_Qclo[S_LEN * D_DIM];
__device__ bf16 g_Kchi[S_LEN * D_DIM];
__device__ bf16 g_Kclo[S_LEN * D_DIM];
__device__ bf16 g_Hhi [S_LEN * HID_DIM];
__device__ bf16 g_Hlo [S_LEN * HID_DIM];
__device__ bf16 g_Ahi [S_LEN * D_DIM];
__device__ bf16 g_Alo [S_LEN * D_DIM];

// bf16 hi/lo weight copies, K-major [N][K]
__device__ bf16 g_BtS_hi[D_DIM * D_DIM];
__device__ bf16 g_BtS_lo[D_DIM * D_DIM];
__device__ bf16 g_BtC_hi[D_DIM * D_DIM];
__device__ bf16 g_BtC_lo[D_DIM * D_DIM];
__device__ bf16 g_Bt1_hi[HID_DIM * D_DIM];
__device__ bf16 g_Bt1_lo[HID_DIM * D_DIM];
__device__ bf16 g_Bt2_hi[D_DIM * HID_DIM];
__device__ bf16 g_Bt2_lo[D_DIM * HID_DIM];

// ---------------- helpers ----------------
__device__ __forceinline__ uint32_t smem_u32(const void* p) {
    uint32_t a;
    asm("{ .reg .u64 t; cvta.to.shared.u64 t, %1; cvt.u32.u64 %0, t; }" : "=r"(a) : "l"(p));
    return a;
}
__device__ __forceinline__ uint32_t pk2(bf16 a, bf16 b) {
    return (uint32_t)__bfloat16_as_ushort(a) | ((uint32_t)__bfloat16_as_ushort(b) << 16);
}
__device__ __forceinline__ void ldsm4(uint32_t r[4], uint32_t addr) {
    asm volatile("ldmatrix.sync.aligned.m8n8.x4.shared.b16 {%0,%1,%2,%3}, [%4];"
        : "=r"(r[0]), "=r"(r[1]), "=r"(r[2]), "=r"(r[3]) : "r"(addr));
}
__device__ __forceinline__ void ldsm2(uint32_t r[2], uint32_t addr) {
    asm volatile("ldmatrix.sync.aligned.m8n8.x2.shared.b16 {%0,%1}, [%2];"
        : "=r"(r[0]), "=r"(r[1]) : "r"(addr));
}
__device__ __forceinline__ void ldsm2t(uint32_t r[2], uint32_t addr) {
    asm volatile("ldmatrix.sync.aligned.m8n8.x2.trans.shared.b16 {%0,%1}, [%2];"
        : "=r"(r[0]), "=r"(r[1]) : "r"(addr));
}
__device__ __forceinline__ void mma_bf16(float d[4], const uint32_t a[4], const uint32_t b[2]) {
    asm volatile(
        "mma.sync.aligned.m16n8k16.row.col.f32.bf16.bf16.f32 "
        "{%0,%1,%2,%3}, {%4,%5,%6,%7}, {%8,%9}, {%0,%1,%2,%3};"
        : "+f"(d[0]), "+f"(d[1]), "+f"(d[2]), "+f"(d[3])
        : "r"(a[0]), "r"(a[1]), "r"(a[2]), "r"(a[3]), "r"(b[0]), "r"(b[1]));
}

// ---------------- split-bf16 mma.sync GEMM ----------------
// A hi/lo [M,K] K-major; B hi/lo [N,K] K-major. Tile 128x128x32, 256 thr.
// SPLIT=false: C fp32 (+bias,+relu). SPLIT=true: Chi/Clo bf16 hi/lo of result.
#define SMSTR 40

template<bool RELU, bool SPLIT>
__global__ void __launch_bounds__(256, 1) mm_gemm(
    const bf16* __restrict__ Ahi, const bf16* __restrict__ Alo,
    const bf16* __restrict__ Bhi, const bf16* __restrict__ Blo,
    const float* __restrict__ bias, float* __restrict__ C,
    bf16* __restrict__ Chi, bf16* __restrict__ Clo,
    int N, int K)
{
    __shared__ bf16 As_hi[128][SMSTR];
    __shared__ bf16 As_lo[128][SMSTR];
    __shared__ bf16 Bs_hi[128][SMSTR];
    __shared__ bf16 Bs_lo[128][SMSTR];

    const int tid  = threadIdx.x;
    const int warp = tid >> 5;
    const int lane = tid & 31;
    const int bm0  = blockIdx.y * 128;
    const int bn0  = blockIdx.x * 128;
    const int wm   = (warp & 1) * 64;
    const int wn   = (warp >> 1) * 32;

    float acc[4][4][4];
    #pragma unroll
    for (int mt = 0; mt < 4; mt++)
        #pragma unroll
        for (int nt = 0; nt < 4; nt++)
            #pragma unroll
            for (int i = 0; i < 4; i++) acc[mt][nt][i] = 0.f;

    const int a_r = lane & 15;
    const int a_c = (lane >> 4) * 8;
    const int b_r = lane & 7;
    const int b_c = ((lane >> 3) & 1) * 8;

    for (int k0 = 0; k0 < K; k0 += 32) {
        __syncthreads();
        #pragma unroll
        for (int t = 0; t < 2; t++) {
            int i = tid + t * 256;
            int row = i >> 2, seg = (i & 3) * 8;
            size_t ga = (size_t)(bm0 + row) * K + k0 + seg;
            size_t gb = (size_t)(bn0 + row) * K + k0 + seg;
            *(uint4*)&As_hi[row][seg] = *(const uint4*)&Ahi[ga];
            *(uint4*)&As_lo[row][seg] = *(const uint4*)&Alo[ga];
            *(uint4*)&Bs_hi[row][seg] = *(const uint4*)&Bhi[gb];
            *(uint4*)&Bs_lo[row][seg] = *(const uint4*)&Blo[gb];
        }
        __syncthreads();

        #pragma unroll
        for (int ks = 0; ks < 2; ks++) {
            uint32_t ah[4][4], al[4][4], bh[4][2], bl[4][2];
            #pragma unroll
            for (int mt = 0; mt < 4; mt++) {
                int r = wm + mt * 16 + a_r;
                int c = ks * 16 + a_c;
                ldsm4(ah[mt], smem_u32(&As_hi[r][c]));
                ldsm4(al[mt], smem_u32(&As_lo[r][c]));
            }
            #pragma unroll
            for (int nt = 0; nt < 4; nt++) {
                int r = wn + nt * 8 + b_r;
                int c = ks * 16 + b_c;
                ldsm2(bh[nt], smem_u32(&Bs_hi[r][c]));
                ldsm2(bl[nt], smem_u32(&Bs_lo[r][c]));
            }
            #pragma unroll
            for (int mt = 0; mt < 4; mt++)
                #pragma unroll
                for (int nt = 0; nt < 4; nt++) {
                    mma_bf16(acc[mt][nt], ah[mt], bh[nt]);
                    mma_bf16(acc[mt][nt], ah[mt], bl[nt]);
                    mma_bf16(acc[mt][nt], al[mt], bh[nt]);
                }
        }
    }

    #pragma unroll
    for (int mt = 0; mt < 4; mt++) {
        #pragma unroll
        for (int nt = 0; nt < 4; nt++) {
            int row = bm0 + wm + mt * 16 + (lane >> 2);
            int col = bn0 + wn + nt * 8 + (lane & 3) * 2;
            float bv0 = bias[col], bv1 = bias[col + 1];
            float v0 = acc[mt][nt][0] + bv0;
            float v1 = acc[mt][nt][1] + bv1;
            float v2 = acc[mt][nt][2] + bv0;
            float v3 = acc[mt][nt][3] + bv1;
            if (RELU) {
                v0 = fmaxf(v0, 0.f); v1 = fmaxf(v1, 0.f);
                v2 = fmaxf(v2, 0.f); v3 = fmaxf(v3, 0.f);
            }
            if (SPLIT) {
                bf16 h0 = __float2bfloat16(v0), h1 = __float2bfloat16(v1);
                bf16 h2 = __float2bfloat16(v2), h3 = __float2bfloat16(v3);
                size_t o0 = (size_t)row * N + col;
                size_t o1 = (size_t)(row + 8) * N + col;
                *(uint32_t*)&Chi[o0] = pk2(h0, h1);
                *(uint32_t*)&Chi[o1] = pk2(h2, h3);
                *(uint32_t*)&Clo[o0] = pk2(__float2bfloat16(v0 - __bfloat162float(h0)),
                                           __float2bfloat16(v1 - __bfloat162float(h1)));
                *(uint32_t*)&Clo[o1] = pk2(__float2bfloat16(v2 - __bfloat162float(h2)),
                                           __float2bfloat16(v3 - __bfloat162float(h3)));
            } else {
                *(float2*)&C[(size_t)row * N + col]       = make_float2(v0, v1);
                *(float2*)&C[(size_t)(row + 8) * N + col] = make_float2(v2, v3);
            }
        }
    }
}

// ---------------- split-bf16 mma.sync flash attention (K == V) ----------------
// Block: 128 q rows, 8 warps x 16 rows. K tiles of 64. Head dim 64.
#define ASTR 72   // smem row stride (halves)

template<bool CAUSAL>
__global__ void __launch_bounds__(256, 1) mm_attn(
    const bf16* __restrict__ Qhi, const bf16* __restrict__ Qlo,
    const bf16* __restrict__ KVhi, const bf16* __restrict__ KVlo,
    float* __restrict__ Out)
{
    extern __shared__ bf16 smA[];
    bf16* QsH = smA;                 // [128][ASTR]
    bf16* QsL = smA + 128 * ASTR;
    bf16* KsH = smA + 256 * ASTR;    // [64][ASTR]
    bf16* KsL = smA + 320 * ASTR;

    const int h   = blockIdx.y;
    const int q0  = blockIdx.x * 128;
    const int tid = threadIdx.x;
    const int warp = tid >> 5;
    const int lane = tid & 31;
    const int wr  = warp * 16;

    // load Q tile (hi/lo)
    #pragma unroll
    for (int t = 0; t < 4; t++) {
        int i = tid + t * 256;           // 0..1023
        int row = i >> 3, seg = (i & 7) * 8;
        size_t g = (size_t)(q0 + row) * D_DIM + h * 64 + seg;
        *(uint4*)&QsH[row * ASTR + seg] = *(const uint4*)&Qhi[g];
        *(uint4*)&QsL[row * ASTR + seg] = *(const uint4*)&Qlo[g];
    }

    float m0 = -1e30f, m1 = -1e30f, l0 = 0.f, l1 = 0.f;
    float o[8][4];
    #pragma unroll
    for (int dn = 0; dn < 8; dn++)
        #pragma unroll
        for (int i = 0; i < 4; i++) o[dn][i] = 0.f;

    const int r0 = q0 + wr + (lane >> 2);
    const int ntiles = CAUSAL ? (q0 / 64 + 2) : (S_LEN / 64);

    for (int kt = 0; kt < ntiles; kt++) {
        const int t0 = kt * 64;
        __syncthreads();
        #pragma unroll
        for (int t = 0; t < 2; t++) {
            int i = tid + t * 256;       // 0..511
            int row = i >> 3, seg = (i & 7) * 8;
            size_t g = (size_t)(t0 + row) * D_DIM + h * 64 + seg;
            *(uint4*)&KsH[row * ASTR + seg] = *(const uint4*)&KVhi[g];
            *(uint4*)&KsL[row * ASTR + seg] = *(const uint4*)&KVlo[g];
        }
        __syncthreads();

        // ---- S = Q K^T ----
        float s[8][4];
        #pragma unroll
        for (int nt = 0; nt < 8; nt++)
            #pragma unroll
            for (int i = 0; i < 4; i++) s[nt][i] = 0.f;

        #pragma unroll
        for (int ks = 0; ks < 4; ks++) {
            uint32_t ah[4], al[4];
            int ac = ks * 16 + (lane >> 4) * 8;
            ldsm4(ah, smem_u32(&QsH[(wr + (lane & 15)) * ASTR + ac]));
            ldsm4(al, smem_u32(&QsL[(wr + (lane & 15)) * ASTR + ac]));
            #pragma unroll
            for (int nt = 0; nt < 8; nt++) {
                uint32_t bh[2], bl[2];
                int br = nt * 8 + (lane & 7);
                int bc = ks * 16 + ((lane >> 3) & 1) * 8;
                ldsm2(bh, smem_u32(&KsH[br * ASTR + bc]));
                ldsm2(bl, smem_u32(&KsL[br * ASTR + bc]));
                mma_bf16(s[nt], ah, bh);
                mma_bf16(s[nt], ah, bl);
                mma_bf16(s[nt], al, bh);
            }
        }

        // ---- scale + mask + online softmax ----
        float mx0 = -1e30f, mx1 = -1e30f;
        #pragma unroll
        for (int nt = 0; nt < 8; nt++) {
            #pragma unroll
            for (int i = 0; i < 4; i++) s[nt][i] *= 0.125f;
            if (CAUSAL && kt >= ntiles - 2) {
                int col = t0 + nt * 8 + (lane & 3) * 2;
                if (col     > r0)     s[nt][0] = -1e9f;
                if (col + 1 > r0)     s[nt][1] = -1e9f;
                if (col     > r0 + 8) s[nt][2] = -1e9f;
                if (col + 1 > r0 + 8) s[nt][3] = -1e9f;
            }
            mx0 = fmaxf(mx0, fmaxf(s[nt][0], s[nt][1]));
            mx1 = fmaxf(mx1, fmaxf(s[nt][2], s[nt][3]));
        }
        mx0 = fmaxf(mx0, __shfl_xor_sync(0xffffffffu, mx0, 1));
        mx0 = fmaxf(mx0, __shfl_xor_sync(0xffffffffu, mx0, 2));
        mx1 = fmaxf(mx1, __shfl_xor_sync(0xffffffffu, mx1, 1));
        mx1 = fmaxf(mx1, __shfl_xor_sync(0xffffffffu, mx1, 2));

        float mn0 = fmaxf(m0, mx0), mn1 = fmaxf(m1, mx1);
        float al0 = __expf(m0 - mn0), al1 = __expf(m1 - mn1);
        float ls0 = 0.f, ls1 = 0.f;
        #pragma unroll
        for (int nt = 0; nt < 8; nt++) {
            s[nt][0] = __expf(s[nt][0] - mn0);
            s[nt][1] = __expf(s[nt][1] - mn0);
            s[nt][2] = __expf(s[nt][2] - mn1);
            s[nt][3] = __expf(s[nt][3] - mn1);
            ls0 += s[nt][0] + s[nt][1];
            ls1 += s[nt][2] + s[nt][3];
        }
        ls0 += __shfl_xor_sync(0xffffffffu, ls0, 1);
        ls0 += __shfl_xor_sync(0xffffffffu, ls0, 2);
        ls1 += __shfl_xor_sync(0xffffffffu, ls1, 1);
        ls1 += __shfl_xor_sync(0xffffffffu, ls1, 2);
        l0 = l0 * al0 + ls0;
        l1 = l1 * al1 + ls1;
        m0 = mn0; m1 = mn1;
        #pragma unroll
        for (int dn = 0; dn < 8; dn++) {
            o[dn][0] *= al0; o[dn][1] *= al0;
            o[dn][2] *= al1; o[dn][3] *= al1;
        }

        // ---- O += P V  (V == K, read transposed) ----
        #pragma unroll
        for (int kc = 0; kc < 4; kc++) {
            uint32_t pa_h[4], pa_l[4];
            {
                float* p0 = s[2 * kc];
                float* p1 = s[2 * kc + 1];
                bf16 h00 = __float2bfloat16(p0[0]), h01 = __float2bfloat16(p0[1]);
                bf16 h02 = __float2bfloat16(p0[2]), h03 = __float2bfloat16(p0[3]);
                bf16 h10 = __float2bfloat16(p1[0]), h11 = __float2bfloat16(p1[1]);
                bf16 h12 = __float2bfloat16(p1[2]), h13 = __float2bfloat16(p1[3]);
                pa_h[0] = pk2(h00, h01); pa_h[1] = pk2(h02, h03);
                pa_h[2] = pk2(h10, h11); pa_h[3] = pk2(h12, h13);
                pa_l[0] = pk2(__float2bfloat16(p0[0] - __bfloat162float(h00)),
                              __float2bfloat16(p0[1] - __bfloat162float(h01)));
                pa_l[1] = pk2(__float2bfloat16(p0[2] - __bfloat162float(h02)),
                              __float2bfloat16(p0[3] - __bfloat162float(h03)));
                pa_l[2] = pk2(__float2bfloat16(p1[0] - __bfloat162float(h10)),
                              __float2bfloat16(p1[1] - __bfloat162float(h11)));
                pa_l[3] = pk2(__float2bfloat16(p1[2] - __bfloat162float(h12)),
                              __float2bfloat16(p1[3] - __bfloat162float(h13)));
            }
            int vr = kc * 16 + (lane & 15);
            #pragma unroll
            for (int dn = 0; dn < 8; dn++) {
                uint32_t bh[2], bl[2];
                ldsm2t(bh, smem_u32(&KsH[vr * ASTR + dn * 8]));
                ldsm2t(bl, smem_u32(&KsL[vr * ASTR + dn * 8]));
                mma_bf16(o[dn], pa_h, bh);
                mma_bf16(o[dn], pa_h, bl);
                mma_bf16(o[dn], pa_l, bh);
            }
        }
    }

    // ---- write out ----
    float inv0 = 1.f / l0, inv1 = 1.f / l1;
    #pragma unroll
    for (int dn = 0; dn < 8; dn++) {
        int col = h * 64 + dn * 8 + (lane & 3) * 2;
        *(float2*)&Out[(size_t)r0 * D_DIM + col] =
            make_float2(o[dn][0] * inv0, o[dn][1] * inv0);
        *(float2*)&Out[(size_t)(r0 + 8) * D_DIM + col] =
            make_float2(o[dn][2] * inv1, o[dn][3] * inv1);
    }
}

// ---------------- activation fp32 -> bf16 hi/lo split ----------------
__global__ void cvt_act(const float4* __restrict__ x, uint2* __restrict__ hi,
                        uint2* __restrict__ lo, int n4) {
    int i = blockIdx.x * 256 + threadIdx.x;
    if (i >= n4) return;
    float4 v = x[i];
    bf16 h0 = __float2bfloat16(v.x), h1 = __float2bfloat16(v.y);
    bf16 h2 = __float2bfloat16(v.z), h3 = __float2bfloat16(v.w);
    bf16 l0 = __float2bfloat16(v.x - __bfloat162float(h0));
    bf16 l1 = __float2bfloat16(v.y - __bfloat162float(h1));
    bf16 l2 = __float2bfloat16(v.z - __bfloat162float(h2));
    bf16 l3 = __float2bfloat16(v.w - __bfloat162float(h3));
    hi[i] = make_uint2(pk2(h0, h1), pk2(h2, h3));
    lo[i] = make_uint2(pk2(l0, l1), pk2(l2, l3));
}

// ---------------- proj weight: W[h][k][e] -> Bt[n=h*64+e][k] hi/lo ----------------
__global__ void prep_projW(const float* __restrict__ W, bf16* __restrict__ hi,
                           bf16* __restrict__ lo) {
    int idx = blockIdx.x * 256 + threadIdx.x;
    int k = idx & 1023, n = idx >> 10;
    int h = n >> 6, e = n & 63;
    float v = W[(h << 16) + (k << 6) + e];
    bf16 hv = __float2bfloat16(v);
    hi[idx] = hv;
    lo[idx] = __float2bfloat16(v - __bfloat162float(hv));
}

// ---------------- tiled transpose+convert ----------------
__global__ void prep_T(const float* __restrict__ in, bf16* __restrict__ hi,
                       bf16* __restrict__ lo, int R, int C) {
    __shared__ float t[32][33];
    int bx = blockIdx.x * 32, by = blockIdx.y * 32;
    int tx = threadIdx.x, ty = threadIdx.y;
    #pragma unroll
    for (int i = 0; i < 32; i += 8)
        t[ty + i][tx] = in[(size_t)(by + ty + i) * C + bx + tx];
    __syncthreads();
    #pragma unroll
    for (int i = 0; i < 32; i += 8) {
        float v = t[tx][ty + i];
        bf16 hv = __float2bfloat16(v);
        size_t o = (size_t)(bx + ty + i) * R + by + tx;
        hi[o] = hv;
        lo[o] = __float2bfloat16(v - __bfloat162float(hv));
    }
}

// ---------------- fused residual add + LayerNorm ----------------
__device__ __forceinline__ float warpReduceSum(float v) {
    #pragma unroll
    for (int off = 16; off > 0; off >>= 1)
        v += __shfl_xor_sync(0xffffffffu, v, off);
    return v;
}
__device__ __forceinline__ float blockReduceSum(float v, float* sh) {
    int lane = threadIdx.x & 31, w = threadIdx.x >> 5;
    __syncthreads();
    v = warpReduceSum(v);
    if (lane == 0) sh[w] = v;
    __syncthreads();
    if (w == 0) {
        float t = (lane < 8) ? sh[lane] : 0.f;
        t = warpReduceSum(t);
        if (lane == 0) sh[0] = t;
    }
    __syncthreads();
    return sh[0];
}
__global__ void add_ln_kernel(const float* __restrict__ A, const float* __restrict__ Bv,
                              const float* __restrict__ g, const float* __restrict__ beta,
                              float* __restrict__ out) {
    __shared__ float red[8];
    const int row = blockIdx.x;
    const int tid = threadIdx.x;
    float x[4];
    float s = 0.f;
    #pragma unroll
    for (int i = 0; i < 4; i++) {
        int c = tid + i * 256;
        x[i] = A[(size_t)row * D_DIM + c] + Bv[(size_t)row * D_DIM + c];
        s += x[i];
    }
    s = blockReduceSum(s, red);
    const float mu = s * (1.f / D_DIM);
    float v = 0.f;
    #pragma unroll
    for (int i = 0; i < 4; i++) { float d = x[i] - mu; v += d * d; }
    v = blockReduceSum(v, red);
    const float rstd = rsqrtf(v * (1.f / D_DIM) + 1e-5f);
    #pragma unroll
    for (int i = 0; i < 4; i++) {
        int c = tid + i * 256;
        out[(size_t)row * D_DIM + c] = (x[i] - mu) * rstd * g[c] + beta[c];
    }
}

// ---------------- launch ----------------
extern "C" void kernel_launch(void* const* d_in, const int* in_sizes, int n_in,
                              void* d_out, int out_size) {
    const float* y   = (const float*)d_in[0];
    const float* enc = (const float*)d_in[1];
    const float* WqS = (const float*)d_in[2];
    const float* bqS = (const float*)d_in[3];
    const float* WqC = (const float*)d_in[4];
    const float* bqC = (const float*)d_in[5];
    const float* g1  = (const float*)d_in[6];
    const float* be1 = (const float*)d_in[7];
    const float* g2  = (const float*)d_in[8];
    const float* be2 = (const float*)d_in[9];
    const float* g3  = (const float*)d_in[10];
    const float* be3 = (const float*)d_in[11];
    const float* w1  = (const float*)d_in[12];
    const float* b1  = (const float*)d_in[13];
    const float* w2  = (const float*)d_in[14];
    const float* b2  = (const float*)d_in[15];
    float* outp = (float*)d_out;

    float *AO, *y1, *y2, *FF;
    bf16 *Phi, *Plo, *Qchi, *Qclo, *Kchi, *Kclo, *Hhi, *Hlo, *Ahi, *Alo;
    bf16 *BtS_hi, *BtS_lo, *BtC_hi, *BtC_lo, *Bt1_hi, *Bt1_lo, *Bt2_hi, *Bt2_lo;
    cudaGetSymbolAddress((void**)&AO, g_AO);
    cudaGetSymbolAddress((void**)&y1, g_y1);
    cudaGetSymbolAddress((void**)&y2, g_y2);
    cudaGetSymbolAddress((void**)&FF, g_FF);
    cudaGetSymbolAddress((void**)&Phi,  g_Phi);
    cudaGetSymbolAddress((void**)&Plo,  g_Plo);
    cudaGetSymbolAddress((void**)&Qchi, g_Qchi);
    cudaGetSymbolAddress((void**)&Qclo, g_Qclo);
    cudaGetSymbolAddress((void**)&Kchi, g_Kchi);
    cudaGetSymbolAddress((void**)&Kclo, g_Kclo);
    cudaGetSymbolAddress((void**)&Hhi,  g_Hhi);
    cudaGetSymbolAddress((void**)&Hlo,  g_Hlo);
    cudaGetSymbolAddress((void**)&Ahi,  g_Ahi);
    cudaGetSymbolAddress((void**)&Alo,  g_Alo);
    cudaGetSymbolAddress((void**)&BtS_hi, g_BtS_hi);
    cudaGetSymbolAddress((void**)&BtS_lo, g_BtS_lo);
    cudaGetSymbolAddress((void**)&BtC_hi, g_BtC_hi);
    cudaGetSymbolAddress((void**)&BtC_lo, g_BtC_lo);
    cudaGetSymbolAddress((void**)&Bt1_hi, g_Bt1_hi);
    cudaGetSymbolAddress((void**)&Bt1_lo, g_Bt1_lo);
    cudaGetSymbolAddress((void**)&Bt2_hi, g_Bt2_hi);
    cudaGetSymbolAddress((void**)&Bt2_lo, g_Bt2_lo);

    const int ATT_SMEM = (384 * ASTR) * 2;   // 55296 B
    cudaFuncSetAttribute(mm_attn<true>,  cudaFuncAttributeMaxDynamicSharedMemorySize, ATT_SMEM);
    cudaFuncSetAttribute(mm_attn<false>, cudaFuncAttributeMaxDynamicSharedMemorySize, ATT_SMEM);

    // weight prep
    prep_projW<<<(D_DIM * D_DIM) / 256, 256>>>(WqS, BtS_hi, BtS_lo);
    prep_projW<<<(D_DIM * D_DIM) / 256, 256>>>(WqC, BtC_hi, BtC_lo);
    prep_T<<<dim3(HID_DIM / 32, D_DIM / 32), dim3(32, 8)>>>(w1, Bt1_hi, Bt1_lo, D_DIM, HID_DIM);
    prep_T<<<dim3(D_DIM / 32, HID_DIM / 32), dim3(32, 8)>>>(w2, Bt2_hi, Bt2_lo, HID_DIM, D_DIM);

    const int N_SD = S_LEN * D_DIM;

    // P (hi/lo) = y @ WtS + bqS
    cvt_act<<<N_SD / 4 / 256, 256>>>((const float4*)y, (uint2*)Ahi, (uint2*)Alo, N_SD / 4);
    mm_gemm<false, true><<<dim3(D_DIM / 128, S_LEN / 128), 256>>>(
        Ahi, Alo, BtS_hi, BtS_lo, bqS, nullptr, Phi, Plo, D_DIM, D_DIM);

    // self attention (q=k=v=P), causal
    mm_attn<true><<<dim3(S_LEN / 128, H_HEADS), 256, ATT_SMEM>>>(Phi, Plo, Phi, Plo, AO);
    add_ln_kernel<<<S_LEN, 256>>>(y, AO, g1, be1, y1);

    // Qc = y1 @ WtC + bqC
    cvt_act<<<N_SD / 4 / 256, 256>>>((const float4*)y1, (uint2*)Ahi, (uint2*)Alo, N_SD / 4);
    mm_gemm<false, true><<<dim3(D_DIM / 128, S_LEN / 128), 256>>>(
        Ahi, Alo, BtC_hi, BtC_lo, bqC, nullptr, Qchi, Qclo, D_DIM, D_DIM);

    // Kc = enc @ WtC + bqC
    cvt_act<<<N_SD / 4 / 256, 256>>>((const float4*)enc, (uint2*)Ahi, (uint2*)Alo, N_SD / 4);
    mm_gemm<false, true><<<dim3(D_DIM / 128, S_LEN / 128), 256>>>(
        Ahi, Alo, BtC_hi, BtC_lo, bqC, nullptr, Kchi, Kclo, D_DIM, D_DIM);

    // cross attention (k=v), non-causal
    mm_attn<false><<<dim3(S_LEN / 128, H_HEADS), 256, ATT_SMEM>>>(Qchi, Qclo, Kchi, Kclo, AO);
    add_ln_kernel<<<S_LEN, 256>>>(y1, AO, g2, be2, y2);

    // Hd (hi/lo) = relu(y2 @ w1 + b1)
    cvt_act<<<N_SD / 4 / 256, 256>>>((const float4*)y2, (uint2*)Ahi, (uint2*)Alo, N_SD / 4);
    mm_gemm<true, true><<<dim3(HID_DIM / 128, S_LEN / 128), 256>>>(
        Ahi, Alo, Bt1_hi, Bt1_lo, b1, nullptr, Hhi, Hlo, HID_DIM, D_DIM);

    // FF = Hd @ w2 + b2 (fp32)
    mm_gemm<false, false><<<dim3(D_DIM / 128, S_LEN / 128), 256>>>(
        Hhi, Hlo, Bt2_hi, Bt2_lo, b2, FF, nullptr, nullptr, D_DIM, HID_DIM);

    add_ln_kernel<<<S_LEN, 256>>>(y2, FF, g3, be3, outp);
}

// round 11
// speedup vs baseline: 2.7389x; 1.1489x over previous
#include <cuda_runtime.h>
#include <cuda_bf16.h>
#include <cstdint>

#define S_LEN 2048
#define D_DIM 1024
#define H_HEADS 16
#define DH_DIM 64
#define HID_DIM 4096

typedef __nv_bfloat16 bf16;

// ---------------- static scratch ----------------
__device__ float g_AO [S_LEN * D_DIM];
__device__ float g_y1 [S_LEN * D_DIM];
__device__ float g_y2 [S_LEN * D_DIM];
__device__ float g_FF [S_LEN * D_DIM];

__device__ bf16 g_Phi [S_LEN * D_DIM];
__device__ bf16 g_Plo [S_LEN * D_DIM];
__device__ bf16 g_Cat_hi[2 * S_LEN * D_DIM];   // [y1 ; enc] stacked
__device__ bf16 g_Cat_lo[2 * S_LEN * D_DIM];
__device__ bf16 g_QK_hi [2 * S_LEN * D_DIM];   // [Qc ; Kc] stacked
__device__ bf16 g_QK_lo [2 * S_LEN * D_DIM];
__device__ bf16 g_Hhi [S_LEN * HID_DIM];
__device__ bf16 g_Hlo [S_LEN * HID_DIM];
__device__ bf16 g_Ahi [S_LEN * D_DIM];
__device__ bf16 g_Alo [S_LEN * D_DIM];

__device__ bf16 g_BtS_hi[D_DIM * D_DIM];
__device__ bf16 g_BtS_lo[D_DIM * D_DIM];
__device__ bf16 g_BtC_hi[D_DIM * D_DIM];
__device__ bf16 g_BtC_lo[D_DIM * D_DIM];
__device__ bf16 g_Bt1_hi[HID_DIM * D_DIM];
__device__ bf16 g_Bt1_lo[HID_DIM * D_DIM];
__device__ bf16 g_Bt2_hi[D_DIM * HID_DIM];
__device__ bf16 g_Bt2_lo[D_DIM * HID_DIM];

// ---------------- helpers ----------------
__device__ __forceinline__ uint32_t smem_u32(const void* p) {
    uint32_t a;
    asm("{ .reg .u64 t; cvta.to.shared.u64 t, %1; cvt.u32.u64 %0, t; }" : "=r"(a) : "l"(p));
    return a;
}
__device__ __forceinline__ uint32_t pk2(bf16 a, bf16 b) {
    return (uint32_t)__bfloat16_as_ushort(a) | ((uint32_t)__bfloat16_as_ushort(b) << 16);
}
__device__ __forceinline__ void cp16(uint32_t dst, const void* src) {
    asm volatile("cp.async.cg.shared.global [%0], [%1], 16;" :: "r"(dst), "l"(src));
}
#define CP_COMMIT() asm volatile("cp.async.commit_group;" ::: "memory")
#define CP_WAIT(N)  asm volatile("cp.async.wait_group %0;" :: "n"(N) : "memory")
__device__ __forceinline__ void ldsm4(uint32_t r[4], uint32_t addr) {
    asm volatile("ldmatrix.sync.aligned.m8n8.x4.shared.b16 {%0,%1,%2,%3}, [%4];"
        : "=r"(r[0]), "=r"(r[1]), "=r"(r[2]), "=r"(r[3]) : "r"(addr));
}
__device__ __forceinline__ void ldsm2(uint32_t r[2], uint32_t addr) {
    asm volatile("ldmatrix.sync.aligned.m8n8.x2.shared.b16 {%0,%1}, [%2];"
        : "=r"(r[0]), "=r"(r[1]) : "r"(addr));
}
__device__ __forceinline__ void ldsm2t(uint32_t r[2], uint32_t addr) {
    asm volatile("ldmatrix.sync.aligned.m8n8.x2.trans.shared.b16 {%0,%1}, [%2];"
        : "=r"(r[0]), "=r"(r[1]) : "r"(addr));
}
__device__ __forceinline__ void mma_bf16(float d[4], const uint32_t a[4], const uint32_t b[2]) {
    asm volatile(
        "mma.sync.aligned.m16n8k16.row.col.f32.bf16.bf16.f32 "
        "{%0,%1,%2,%3}, {%4,%5,%6,%7}, {%8,%9}, {%0,%1,%2,%3};"
        : "+f"(d[0]), "+f"(d[1]), "+f"(d[2]), "+f"(d[3])
        : "r"(a[0]), "r"(a[1]), "r"(a[2]), "r"(a[3]), "r"(b[0]), "r"(b[1]));
}

// ---------------- double-buffered split-bf16 mma.sync GEMM ----------------
#define SMSTR 40
#define GSTG (128 * SMSTR)   // elements per array per stage

__device__ __forceinline__ void gemm_issue(
    bf16* base, const bf16* Ahi, const bf16* Alo, const bf16* Bhi, const bf16* Blo,
    int bm0, int bn0, int K, int k0, int tid)
{
    #pragma unroll
    for (int t = 0; t < 2; t++) {
        int i = tid + t * 256;
        int row = i >> 2, seg = (i & 3) * 8;
        size_t ga = (size_t)(bm0 + row) * K + k0 + seg;
        size_t gb = (size_t)(bn0 + row) * K + k0 + seg;
        int so = row * SMSTR + seg;
        cp16(smem_u32(base + so),            Ahi + ga);
        cp16(smem_u32(base + GSTG + so),     Alo + ga);
        cp16(smem_u32(base + 2 * GSTG + so), Bhi + gb);
        cp16(smem_u32(base + 3 * GSTG + so), Blo + gb);
    }
}

template<bool RELU, bool SPLIT>
__global__ void __launch_bounds__(256, 1) mm_gemm(
    const bf16* __restrict__ Ahi, const bf16* __restrict__ Alo,
    const bf16* __restrict__ Bhi, const bf16* __restrict__ Blo,
    const float* __restrict__ bias, float* __restrict__ C,
    bf16* __restrict__ Chi, bf16* __restrict__ Clo,
    int N, int K)
{
    extern __shared__ bf16 smg[];

    const int tid  = threadIdx.x;
    const int warp = tid >> 5;
    const int lane = tid & 31;
    const int bm0  = blockIdx.y * 128;
    const int bn0  = blockIdx.x * 128;
    const int wm   = (warp & 1) * 64;
    const int wn   = (warp >> 1) * 32;

    float acc[4][4][4];
    #pragma unroll
    for (int mt = 0; mt < 4; mt++)
        #pragma unroll
        for (int nt = 0; nt < 4; nt++)
            #pragma unroll
            for (int i = 0; i < 4; i++) acc[mt][nt][i] = 0.f;

    const int a_r = lane & 15;
    const int a_c = (lane >> 4) * 8;
    const int b_r = lane & 7;
    const int b_c = ((lane >> 3) & 1) * 8;
    const int nch = K >> 5;

    gemm_issue(smg, Ahi, Alo, Bhi, Blo, bm0, bn0, K, 0, tid);
    CP_COMMIT();

    for (int ch = 0; ch < nch; ch++) {
        bf16* cur = smg + (ch & 1) * 4 * GSTG;
        if (ch + 1 < nch) {
            gemm_issue(smg + ((ch + 1) & 1) * 4 * GSTG, Ahi, Alo, Bhi, Blo,
                       bm0, bn0, K, (ch + 1) << 5, tid);
            CP_COMMIT();
            CP_WAIT(1);
        } else {
            CP_WAIT(0);
        }
        __syncthreads();

        bf16* AsH = cur;
        bf16* AsL = cur + GSTG;
        bf16* BsH = cur + 2 * GSTG;
        bf16* BsL = cur + 3 * GSTG;

        #pragma unroll
        for (int ks = 0; ks < 2; ks++) {
            uint32_t ah[4][4], al[4][4], bh[4][2], bl[4][2];
            #pragma unroll
            for (int mt = 0; mt < 4; mt++) {
                int r = wm + mt * 16 + a_r;
                int c = ks * 16 + a_c;
                ldsm4(ah[mt], smem_u32(&AsH[r * SMSTR + c]));
                ldsm4(al[mt], smem_u32(&AsL[r * SMSTR + c]));
            }
            #pragma unroll
            for (int nt = 0; nt < 4; nt++) {
                int r = wn + nt * 8 + b_r;
                int c = ks * 16 + b_c;
                ldsm2(bh[nt], smem_u32(&BsH[r * SMSTR + c]));
                ldsm2(bl[nt], smem_u32(&BsL[r * SMSTR + c]));
            }
            #pragma unroll
            for (int mt = 0; mt < 4; mt++)
                #pragma unroll
                for (int nt = 0; nt < 4; nt++) {
                    mma_bf16(acc[mt][nt], ah[mt], bh[nt]);
                    mma_bf16(acc[mt][nt], ah[mt], bl[nt]);
                    mma_bf16(acc[mt][nt], al[mt], bh[nt]);
                }
        }
        __syncthreads();
    }

    #pragma unroll
    for (int mt = 0; mt < 4; mt++) {
        #pragma unroll
        for (int nt = 0; nt < 4; nt++) {
            int row = bm0 + wm + mt * 16 + (lane >> 2);
            int col = bn0 + wn + nt * 8 + (lane & 3) * 2;
            float bv0 = bias[col], bv1 = bias[col + 1];
            float v0 = acc[mt][nt][0] + bv0;
            float v1 = acc[mt][nt][1] + bv1;
            float v2 = acc[mt][nt][2] + bv0;
            float v3 = acc[mt][nt][3] + bv1;
            if (RELU) {
                v0 = fmaxf(v0, 0.f); v1 = fmaxf(v1, 0.f);
                v2 = fmaxf(v2, 0.f); v3 = fmaxf(v3, 0.f);
            }
            if (SPLIT) {
                bf16 h0 = __float2bfloat16(v0), h1 = __float2bfloat16(v1);
                bf16 h2 = __float2bfloat16(v2), h3 = __float2bfloat16(v3);
                size_t o0 = (size_t)row * N + col;
                size_t o1 = (size_t)(row + 8) * N + col;
                *(uint32_t*)&Chi[o0] = pk2(h0, h1);
                *(uint32_t*)&Chi[o1] = pk2(h2, h3);
                *(uint32_t*)&Clo[o0] = pk2(__float2bfloat16(v0 - __bfloat162float(h0)),
                                           __float2bfloat16(v1 - __bfloat162float(h1)));
                *(uint32_t*)&Clo[o1] = pk2(__float2bfloat16(v2 - __bfloat162float(h2)),
                                           __float2bfloat16(v3 - __bfloat162float(h3)));
            } else {
                *(float2*)&C[(size_t)row * N + col]       = make_float2(v0, v1);
                *(float2*)&C[(size_t)(row + 8) * N + col] = make_float2(v2, v3);
            }
        }
    }
}

// ---------------- double-buffered split-bf16 flash attention (K == V) ----------------
#define ASTR 72
#define QELT (128 * ASTR)
#define KELT (64 * ASTR)

__device__ __forceinline__ void attn_issueK(
    bf16* KsH, bf16* KsL, const bf16* KVhi, const bf16* KVlo,
    int t0, int h, int tid)
{
    #pragma unroll
    for (int t = 0; t < 2; t++) {
        int i = tid + t * 256;
        int row = i >> 3, seg = (i & 7) * 8;
        size_t g = (size_t)(t0 + row) * D_DIM + h * 64 + seg;
        cp16(smem_u32(KsH + row * ASTR + seg), KVhi + g);
        cp16(smem_u32(KsL + row * ASTR + seg), KVlo + g);
    }
}

template<bool CAUSAL>
__global__ void __launch_bounds__(256, 1) mm_attn(
    const bf16* __restrict__ Qhi, const bf16* __restrict__ Qlo,
    const bf16* __restrict__ KVhi, const bf16* __restrict__ KVlo,
    float* __restrict__ Out)
{
    extern __shared__ bf16 smA[];
    bf16* QsH = smA;
    bf16* QsL = smA + QELT;
    bf16* Kst = smA + 2 * QELT;    // 2 stages x (KsH, KsL)

    const int h   = blockIdx.y;
    const int q0  = blockIdx.x * 128;
    const int tid = threadIdx.x;
    const int warp = tid >> 5;
    const int lane = tid & 31;
    const int wr  = warp * 16;

    // Q tile via cp.async (group 0, together with K tile 0)
    #pragma unroll
    for (int t = 0; t < 4; t++) {
        int i = tid + t * 256;
        int row = i >> 3, seg = (i & 7) * 8;
        size_t g = (size_t)(q0 + row) * D_DIM + h * 64 + seg;
        cp16(smem_u32(QsH + row * ASTR + seg), Qhi + g);
        cp16(smem_u32(QsL + row * ASTR + seg), Qlo + g);
    }
    attn_issueK(Kst, Kst + KELT, KVhi, KVlo, 0, h, tid);
    CP_COMMIT();

    float m0 = -1e30f, m1 = -1e30f, l0 = 0.f, l1 = 0.f;
    float o[8][4];
    #pragma unroll
    for (int dn = 0; dn < 8; dn++)
        #pragma unroll
        for (int i = 0; i < 4; i++) o[dn][i] = 0.f;

    const int r0 = q0 + wr + (lane >> 2);
    const int ntiles = CAUSAL ? (q0 / 64 + 2) : (S_LEN / 64);

    for (int kt = 0; kt < ntiles; kt++) {
        const int t0 = kt * 64;
        bf16* KsH = Kst + (kt & 1) * 2 * KELT;
        bf16* KsL = KsH + KELT;
        if (kt + 1 < ntiles) {
            bf16* nH = Kst + ((kt + 1) & 1) * 2 * KELT;
            attn_issueK(nH, nH + KELT, KVhi, KVlo, (kt + 1) * 64, h, tid);
            CP_COMMIT();
            CP_WAIT(1);
        } else {
            CP_WAIT(0);
        }
        __syncthreads();

        // ---- S = Q K^T ----
        float s[8][4];
        #pragma unroll
        for (int nt = 0; nt < 8; nt++)
            #pragma unroll
            for (int i = 0; i < 4; i++) s[nt][i] = 0.f;

        #pragma unroll
        for (int ks = 0; ks < 4; ks++) {
            uint32_t ah[4], al[4];
            int ac = ks * 16 + (lane >> 4) * 8;
            ldsm4(ah, smem_u32(&QsH[(wr + (lane & 15)) * ASTR + ac]));
            ldsm4(al, smem_u32(&QsL[(wr + (lane & 15)) * ASTR + ac]));
            #pragma unroll
            for (int nt = 0; nt < 8; nt++) {
                uint32_t bh[2], bl[2];
                int br = nt * 8 + (lane & 7);
                int bc = ks * 16 + ((lane >> 3) & 1) * 8;
                ldsm2(bh, smem_u32(&KsH[br * ASTR + bc]));
                ldsm2(bl, smem_u32(&KsL[br * ASTR + bc]));
                mma_bf16(s[nt], ah, bh);
                mma_bf16(s[nt], ah, bl);
                mma_bf16(s[nt], al, bh);
            }
        }

        // ---- scale + mask + online softmax ----
        float mx0 = -1e30f, mx1 = -1e30f;
        #pragma unroll
        for (int nt = 0; nt < 8; nt++) {
            #pragma unroll
            for (int i = 0; i < 4; i++) s[nt][i] *= 0.125f;
            if (CAUSAL && kt >= ntiles - 2) {
                int col = t0 + nt * 8 + (lane & 3) * 2;
                if (col     > r0)     s[nt][0] = -1e9f;
                if (col + 1 > r0)     s[nt][1] = -1e9f;
                if (col     > r0 + 8) s[nt][2] = -1e9f;
                if (col + 1 > r0 + 8) s[nt][3] = -1e9f;
            }
            mx0 = fmaxf(mx0, fmaxf(s[nt][0], s[nt][1]));
            mx1 = fmaxf(mx1, fmaxf(s[nt][2], s[nt][3]));
        }
        mx0 = fmaxf(mx0, __shfl_xor_sync(0xffffffffu, mx0, 1));
        mx0 = fmaxf(mx0, __shfl_xor_sync(0xffffffffu, mx0, 2));
        mx1 = fmaxf(mx1, __shfl_xor_sync(0xffffffffu, mx1, 1));
        mx1 = fmaxf(mx1, __shfl_xor_sync(0xffffffffu, mx1, 2));

        float mn0 = fmaxf(m0, mx0), mn1 = fmaxf(m1, mx1);
        float al0 = __expf(m0 - mn0), al1 = __expf(m1 - mn1);
        float ls0 = 0.f, ls1 = 0.f;
        #pragma unroll
        for (int nt = 0; nt < 8; nt++) {
            s[nt][0] = __expf(s[nt][0] - mn0);
            s[nt][1] = __expf(s[nt][1] - mn0);
            s[nt][2] = __expf(s[nt][2] - mn1);
            s[nt][3] = __expf(s[nt][3] - mn1);
            ls0 += s[nt][0] + s[nt][1];
            ls1 += s[nt][2] + s[nt][3];
        }
        ls0 += __shfl_xor_sync(0xffffffffu, ls0, 1);
        ls0 += __shfl_xor_sync(0xffffffffu, ls0, 2);
        ls1 += __shfl_xor_sync(0xffffffffu, ls1, 1);
        ls1 += __shfl_xor_sync(0xffffffffu, ls1, 2);
        l0 = l0 * al0 + ls0;
        l1 = l1 * al1 + ls1;
        m0 = mn0; m1 = mn1;
        #pragma unroll
        for (int dn = 0; dn < 8; dn++) {
            o[dn][0] *= al0; o[dn][1] *= al0;
            o[dn][2] *= al1; o[dn][3] *= al1;
        }

        // ---- O += P V  (V == K, transposed reads) ----
        #pragma unroll
        for (int kc = 0; kc < 4; kc++) {
            uint32_t pa_h[4], pa_l[4];
            {
                float* p0 = s[2 * kc];
                float* p1 = s[2 * kc + 1];
                bf16 h00 = __float2bfloat16(p0[0]), h01 = __float2bfloat16(p0[1]);
                bf16 h02 = __float2bfloat16(p0[2]), h03 = __float2bfloat16(p0[3]);
                bf16 h10 = __float2bfloat16(p1[0]), h11 = __float2bfloat16(p1[1]);
                bf16 h12 = __float2bfloat16(p1[2]), h13 = __float2bfloat16(p1[3]);
                pa_h[0] = pk2(h00, h01); pa_h[1] = pk2(h02, h03);
                pa_h[2] = pk2(h10, h11); pa_h[3] = pk2(h12, h13);
                pa_l[0] = pk2(__float2bfloat16(p0[0] - __bfloat162float(h00)),
                              __float2bfloat16(p0[1] - __bfloat162float(h01)));
                pa_l[1] = pk2(__float2bfloat16(p0[2] - __bfloat162float(h02)),
                              __float2bfloat16(p0[3] - __bfloat162float(h03)));
                pa_l[2] = pk2(__float2bfloat16(p1[0] - __bfloat162float(h10)),
                              __float2bfloat16(p1[1] - __bfloat162float(h11)));
                pa_l[3] = pk2(__float2bfloat16(p1[2] - __bfloat162float(h12)),
                              __float2bfloat16(p1[3] - __bfloat162float(h13)));
            }
            int vr = kc * 16 + (lane & 15);
            #pragma unroll
            for (int dn = 0; dn < 8; dn++) {
                uint32_t bh[2], bl[2];
                ldsm2t(bh, smem_u32(&KsH[vr * ASTR + dn * 8]));
                ldsm2t(bl, smem_u32(&KsL[vr * ASTR + dn * 8]));
                mma_bf16(o[dn], pa_h, bh);
                mma_bf16(o[dn], pa_h, bl);
                mma_bf16(o[dn], pa_l, bh);
            }
        }
        __syncthreads();
    }

    float inv0 = 1.f / l0, inv1 = 1.f / l1;
    #pragma unroll
    for (int dn = 0; dn < 8; dn++) {
        int col = h * 64 + dn * 8 + (lane & 3) * 2;
        *(float2*)&Out[(size_t)r0 * D_DIM + col] =
            make_float2(o[dn][0] * inv0, o[dn][1] * inv0);
        *(float2*)&Out[(size_t)(r0 + 8) * D_DIM + col] =
            make_float2(o[dn][2] * inv1, o[dn][3] * inv1);
    }
}

// ---------------- activation fp32 -> bf16 hi/lo split ----------------
__global__ void cvt_act(const float4* __restrict__ x, uint2* __restrict__ hi,
                        uint2* __restrict__ lo, int n4) {
    int i = blockIdx.x * 256 + threadIdx.x;
    if (i >= n4) return;
    float4 v = x[i];
    bf16 h0 = __float2bfloat16(v.x), h1 = __float2bfloat16(v.y);
    bf16 h2 = __float2bfloat16(v.z), h3 = __float2bfloat16(v.w);
    bf16 l0 = __float2bfloat16(v.x - __bfloat162float(h0));
    bf16 l1 = __float2bfloat16(v.y - __bfloat162float(h1));
    bf16 l2 = __float2bfloat16(v.z - __bfloat162float(h2));
    bf16 l3 = __float2bfloat16(v.w - __bfloat162float(h3));
    hi[i] = make_uint2(pk2(h0, h1), pk2(h2, h3));
    lo[i] = make_uint2(pk2(l0, l1), pk2(l2, l3));
}

// ---------------- weight prep ----------------
__global__ void prep_projW(const float* __restrict__ W, bf16* __restrict__ hi,
                           bf16* __restrict__ lo) {
    int idx = blockIdx.x * 256 + threadIdx.x;
    int k = idx & 1023, n = idx >> 10;
    int h = n >> 6, e = n & 63;
    float v = W[(h << 16) + (k << 6) + e];
    bf16 hv = __float2bfloat16(v);
    hi[idx] = hv;
    lo[idx] = __float2bfloat16(v - __bfloat162float(hv));
}

__global__ void prep_T(const float* __restrict__ in, bf16* __restrict__ hi,
                       bf16* __restrict__ lo, int R, int C) {
    __shared__ float t[32][33];
    int bx = blockIdx.x * 32, by = blockIdx.y * 32;
    int tx = threadIdx.x, ty = threadIdx.y;
    #pragma unroll
    for (int i = 0; i < 32; i += 8)
        t[ty + i][tx] = in[(size_t)(by + ty + i) * C + bx + tx];
    __syncthreads();
    #pragma unroll
    for (int i = 0; i < 32; i += 8) {
        float v = t[tx][ty + i];
        bf16 hv = __float2bfloat16(v);
        size_t o = (size_t)(bx + ty + i) * R + by + tx;
        hi[o] = hv;
        lo[o] = __float2bfloat16(v - __bfloat162float(hv));
    }
}

// ---------------- fused residual add + LayerNorm (+optional hi/lo split out) ----------------
__device__ __forceinline__ float warpReduceSum(float v) {
    #pragma unroll
    for (int off = 16; off > 0; off >>= 1)
        v += __shfl_xor_sync(0xffffffffu, v, off);
    return v;
}
__device__ __forceinline__ float blockReduceSum(float v, float* sh) {
    int lane = threadIdx.x & 31, w = threadIdx.x >> 5;
    __syncthreads();
    v = warpReduceSum(v);
    if (lane == 0) sh[w] = v;
    __syncthreads();
    if (w == 0) {
        float t = (lane < 8) ? sh[lane] : 0.f;
        t = warpReduceSum(t);
        if (lane == 0) sh[0] = t;
    }
    __syncthreads();
    return sh[0];
}

template<bool SPLIT>
__global__ void add_ln_kernel(const float* __restrict__ A, const float* __restrict__ Bv,
                              const float* __restrict__ g, const float* __restrict__ beta,
                              float* __restrict__ out,
                              bf16* __restrict__ hi, bf16* __restrict__ lo) {
    __shared__ float red[8];
    const int row = blockIdx.x;
    const int tid = threadIdx.x;
    float x[4];
    float s = 0.f;
    #pragma unroll
    for (int i = 0; i < 4; i++) {
        int c = tid + i * 256;
        x[i] = A[(size_t)row * D_DIM + c] + Bv[(size_t)row * D_DIM + c];
        s += x[i];
    }
    s = blockReduceSum(s, red);
    const float mu = s * (1.f / D_DIM);
    float v = 0.f;
    #pragma unroll
    for (int i = 0; i < 4; i++) { float d = x[i] - mu; v += d * d; }
    v = blockReduceSum(v, red);
    const float rstd = rsqrtf(v * (1.f / D_DIM) + 1e-5f);
    #pragma unroll
    for (int i = 0; i < 4; i++) {
        int c = tid + i * 256;
        float r = (x[i] - mu) * rstd * g[c] + beta[c];
        out[(size_t)row * D_DIM + c] = r;
        if (SPLIT) {
            bf16 hv = __float2bfloat16(r);
            hi[(size_t)row * D_DIM + c] = hv;
            lo[(size_t)row * D_DIM + c] = __float2bfloat16(r - __bfloat162float(hv));
        }
    }
}

// ---------------- launch ----------------
extern "C" void kernel_launch(void* const* d_in, const int* in_sizes, int n_in,
                              void* d_out, int out_size) {
    const float* y   = (const float*)d_in[0];
    const float* enc = (const float*)d_in[1];
    const float* WqS = (const float*)d_in[2];
    const float* bqS = (const float*)d_in[3];
    const float* WqC = (const float*)d_in[4];
    const float* bqC = (const float*)d_in[5];
    const float* g1  = (const float*)d_in[6];
    const float* be1 = (const float*)d_in[7];
    const float* g2  = (const float*)d_in[8];
    const float* be2 = (const float*)d_in[9];
    const float* g3  = (const float*)d_in[10];
    const float* be3 = (const float*)d_in[11];
    const float* w1  = (const float*)d_in[12];
    const float* b1  = (const float*)d_in[13];
    const float* w2  = (const float*)d_in[14];
    const float* b2  = (const float*)d_in[15];
    float* outp = (float*)d_out;

    float *AO, *y1, *y2, *FF;
    bf16 *Phi, *Plo, *CatHi, *CatLo, *QKhi, *QKlo, *Hhi, *Hlo, *Ahi, *Alo;
    bf16 *BtS_hi, *BtS_lo, *BtC_hi, *BtC_lo, *Bt1_hi, *Bt1_lo, *Bt2_hi, *Bt2_lo;
    cudaGetSymbolAddress((void**)&AO, g_AO);
    cudaGetSymbolAddress((void**)&y1, g_y1);
    cudaGetSymbolAddress((void**)&y2, g_y2);
    cudaGetSymbolAddress((void**)&FF, g_FF);
    cudaGetSymbolAddress((void**)&Phi,   g_Phi);
    cudaGetSymbolAddress((void**)&Plo,   g_Plo);
    cudaGetSymbolAddress((void**)&CatHi, g_Cat_hi);
    cudaGetSymbolAddress((void**)&CatLo, g_Cat_lo);
    cudaGetSymbolAddress((void**)&QKhi,  g_QK_hi);
    cudaGetSymbolAddress((void**)&QKlo,  g_QK_lo);
    cudaGetSymbolAddress((void**)&Hhi,   g_Hhi);
    cudaGetSymbolAddress((void**)&Hlo,   g_Hlo);
    cudaGetSymbolAddress((void**)&Ahi,   g_Ahi);
    cudaGetSymbolAddress((void**)&Alo,   g_Alo);
    cudaGetSymbolAddress((void**)&BtS_hi, g_BtS_hi);
    cudaGetSymbolAddress((void**)&BtS_lo, g_BtS_lo);
    cudaGetSymbolAddress((void**)&BtC_hi, g_BtC_hi);
    cudaGetSymbolAddress((void**)&BtC_lo, g_BtC_lo);
    cudaGetSymbolAddress((void**)&Bt1_hi, g_Bt1_hi);
    cudaGetSymbolAddress((void**)&Bt1_lo, g_Bt1_lo);
    cudaGetSymbolAddress((void**)&Bt2_hi, g_Bt2_hi);
    cudaGetSymbolAddress((void**)&Bt2_lo, g_Bt2_lo);

    const int GEMM_SMEM = 2 * 4 * GSTG * 2;            // 81920 B
    const int ATT_SMEM  = (2 * QELT + 4 * KELT) * 2;   // 73728 B
    cudaFuncSetAttribute(mm_gemm<false, true>,  cudaFuncAttributeMaxDynamicSharedMemorySize, GEMM_SMEM);
    cudaFuncSetAttribute(mm_gemm<true, true>,   cudaFuncAttributeMaxDynamicSharedMemorySize, GEMM_SMEM);
    cudaFuncSetAttribute(mm_gemm<false, false>, cudaFuncAttributeMaxDynamicSharedMemorySize, GEMM_SMEM);
    cudaFuncSetAttribute(mm_attn<true>,  cudaFuncAttributeMaxDynamicSharedMemorySize, ATT_SMEM);
    cudaFuncSetAttribute(mm_attn<false>, cudaFuncAttributeMaxDynamicSharedMemorySize, ATT_SMEM);

    // weight prep
    prep_projW<<<(D_DIM * D_DIM) / 256, 256>>>(WqS, BtS_hi, BtS_lo);
    prep_projW<<<(D_DIM * D_DIM) / 256, 256>>>(WqC, BtC_hi, BtC_lo);
    prep_T<<<dim3(HID_DIM / 32, D_DIM / 32), dim3(32, 8)>>>(w1, Bt1_hi, Bt1_lo, D_DIM, HID_DIM);
    prep_T<<<dim3(D_DIM / 32, HID_DIM / 32), dim3(32, 8)>>>(w2, Bt2_hi, Bt2_lo, HID_DIM, D_DIM);

    const int N_SD = S_LEN * D_DIM;

    // convert inputs: y -> A, enc -> Cat second half
    cvt_act<<<N_SD / 4 / 256, 256>>>((const float4*)y, (uint2*)Ahi, (uint2*)Alo, N_SD / 4);
    cvt_act<<<N_SD / 4 / 256, 256>>>((const float4*)enc,
        (uint2*)(CatHi + N_SD), (uint2*)(CatLo + N_SD), N_SD / 4);

    // P (hi/lo) = y @ WtS + bqS
    mm_gemm<false, true><<<dim3(D_DIM / 128, S_LEN / 128), 256, GEMM_SMEM>>>(
        Ahi, Alo, BtS_hi, BtS_lo, bqS, nullptr, Phi, Plo, D_DIM, D_DIM);

    // self attention (q=k=v=P), causal
    mm_attn<true><<<dim3(S_LEN / 128, H_HEADS), 256, ATT_SMEM>>>(Phi, Plo, Phi, Plo, AO);
    // y1 = LN(y + AO), also split into Cat first half
    add_ln_kernel<true><<<S_LEN, 256>>>(y, AO, g1, be1, y1, CatHi, CatLo);

    // [Qc ; Kc] = [y1 ; enc] @ WtC + bqC   (one combined GEMM, M = 4096)
    mm_gemm<false, true><<<dim3(D_DIM / 128, 2 * S_LEN / 128), 256, GEMM_SMEM>>>(
        CatHi, CatLo, BtC_hi, BtC_lo, bqC, nullptr, QKhi, QKlo, D_DIM, D_DIM);

    // cross attention (k=v), non-causal
    mm_attn<false><<<dim3(S_LEN / 128, H_HEADS), 256, ATT_SMEM>>>(
        QKhi, QKlo, QKhi + N_SD, QKlo + N_SD, AO);
    // y2 = LN(y1 + AO), split into A
    add_ln_kernel<true><<<S_LEN, 256>>>(y1, AO, g2, be2, y2, Ahi, Alo);

    // Hd (hi/lo) = relu(y2 @ w1 + b1)
    mm_gemm<true, true><<<dim3(HID_DIM / 128, S_LEN / 128), 256, GEMM_SMEM>>>(
        Ahi, Alo, Bt1_hi, Bt1_lo, b1, nullptr, Hhi, Hlo, HID_DIM, D_DIM);

    // FF = Hd @ w2 + b2 (fp32)
    mm_gemm<false, false><<<dim3(D_DIM / 128, S_LEN / 128), 256, GEMM_SMEM>>>(
        Hhi, Hlo, Bt2_hi, Bt2_lo, b2, FF, nullptr, nullptr, D_DIM, HID_DIM);

    // out = LN(y2 + FF)
    add_ln_kernel<false><<<S_LEN, 256>>>(y2, FF, g3, be3, outp, nullptr, nullptr);
}

// round 14
// speedup vs baseline: 2.9527x; 1.0781x over previous
#include <cuda_runtime.h>
#include <cuda_bf16.h>
#include <cstdint>

#define S_LEN 2048
#define D_DIM 1024
#define H_HEADS 16
#define DH_DIM 64
#define HID_DIM 4096

typedef __nv_bfloat16 bf16;

// ---------------- static scratch ----------------
__device__ float g_AO [S_LEN * D_DIM];
__device__ float g_y1 [S_LEN * D_DIM];
__device__ float g_y2 [S_LEN * D_DIM];
__device__ float g_FF [S_LEN * D_DIM];

__device__ bf16 g_Phi [S_LEN * D_DIM];
__device__ bf16 g_Plo [S_LEN * D_DIM];
__device__ bf16 g_Cat_hi[2 * S_LEN * D_DIM];   // [y1 ; enc] stacked
__device__ bf16 g_Cat_lo[2 * S_LEN * D_DIM];
__device__ bf16 g_QK_hi [2 * S_LEN * D_DIM];   // [Qc ; Kc] stacked
__device__ bf16 g_QK_lo [2 * S_LEN * D_DIM];
__device__ bf16 g_Hhi [S_LEN * HID_DIM];
__device__ bf16 g_Hlo [S_LEN * HID_DIM];
__device__ bf16 g_Ahi [S_LEN * D_DIM];
__device__ bf16 g_Alo [S_LEN * D_DIM];

__device__ bf16 g_BtS_hi[D_DIM * D_DIM];
__device__ bf16 g_BtS_lo[D_DIM * D_DIM];
__device__ bf16 g_BtC_hi[D_DIM * D_DIM];
__device__ bf16 g_BtC_lo[D_DIM * D_DIM];
__device__ bf16 g_Bt1_hi[HID_DIM * D_DIM];
__device__ bf16 g_Bt1_lo[HID_DIM * D_DIM];
__device__ bf16 g_Bt2_hi[D_DIM * HID_DIM];
__device__ bf16 g_Bt2_lo[D_DIM * HID_DIM];

// ---------------- helpers ----------------
__device__ __forceinline__ uint32_t smem_u32(const void* p) {
    uint32_t a;
    asm("{ .reg .u64 t; cvta.to.shared.u64 t, %1; cvt.u32.u64 %0, t; }" : "=r"(a) : "l"(p));
    return a;
}
__device__ __forceinline__ uint32_t pk2(bf16 a, bf16 b) {
    return (uint32_t)__bfloat16_as_ushort(a) | ((uint32_t)__bfloat16_as_ushort(b) << 16);
}
// packed convert: a -> low half, b -> high half (rn rounding, same as __float2bfloat16)
__device__ __forceinline__ uint32_t pk2f(float a, float b) {
    uint32_t r;
    asm("cvt.rn.bf16x2.f32 %0, %1, %2;" : "=r"(r) : "f"(b), "f"(a));
    return r;
}
__device__ __forceinline__ void cp16(uint32_t dst, const void* src) {
    asm volatile("cp.async.cg.shared.global [%0], [%1], 16;" :: "r"(dst), "l"(src));
}
#define CP_COMMIT() asm volatile("cp.async.commit_group;" ::: "memory")
#define CP_WAIT(N)  asm volatile("cp.async.wait_group %0;" :: "n"(N) : "memory")
__device__ __forceinline__ void ldsm4(uint32_t r[4], uint32_t addr) {
    asm volatile("ldmatrix.sync.aligned.m8n8.x4.shared.b16 {%0,%1,%2,%3}, [%4];"
        : "=r"(r[0]), "=r"(r[1]), "=r"(r[2]), "=r"(r[3]) : "r"(addr));
}
__device__ __forceinline__ void ldsm2(uint32_t r[2], uint32_t addr) {
    asm volatile("ldmatrix.sync.aligned.m8n8.x2.shared.b16 {%0,%1}, [%2];"
        : "=r"(r[0]), "=r"(r[1]) : "r"(addr));
}
__device__ __forceinline__ void ldsm2t(uint32_t r[2], uint32_t addr) {
    asm volatile("ldmatrix.sync.aligned.m8n8.x2.trans.shared.b16 {%0,%1}, [%2];"
        : "=r"(r[0]), "=r"(r[1]) : "r"(addr));
}
__device__ __forceinline__ void mma_bf16(float d[4], const uint32_t a[4], const uint32_t b[2]) {
    asm volatile(
        "mma.sync.aligned.m16n8k16.row.col.f32.bf16.bf16.f32 "
        "{%0,%1,%2,%3}, {%4,%5,%6,%7}, {%8,%9}, {%0,%1,%2,%3};"
        : "+f"(d[0]), "+f"(d[1]), "+f"(d[2]), "+f"(d[3])
        : "r"(a[0]), "r"(a[1]), "r"(a[2]), "r"(a[3]), "r"(b[0]), "r"(b[1]));
}

// ---------------- 3-stage split-bf16 mma.sync GEMM ----------------
#define SMSTR 40
#define GSTG (128 * SMSTR)   // elements per array per stage

__device__ __forceinline__ void gemm_issue(
    bf16* base, const bf16* Ahi, const bf16* Alo, const bf16* Bhi, const bf16* Blo,
    int bm0, int bn0, int K, int k0, int tid)
{
    #pragma unroll
    for (int t = 0; t < 2; t++) {
        int i = tid + t * 256;
        int row = i >> 2, seg = (i & 3) * 8;
        size_t ga = (size_t)(bm0 + row) * K + k0 + seg;
        size_t gb = (size_t)(bn0 + row) * K + k0 + seg;
        int so = row * SMSTR + seg;
        cp16(smem_u32(base + so),            Ahi + ga);
        cp16(smem_u32(base + GSTG + so),     Alo + ga);
        cp16(smem_u32(base + 2 * GSTG + so), Bhi + gb);
        cp16(smem_u32(base + 3 * GSTG + so), Blo + gb);
    }
}

template<bool RELU, bool SPLIT>
__global__ void __launch_bounds__(256, 1) mm_gemm(
    const bf16* __restrict__ Ahi, const bf16* __restrict__ Alo,
    const bf16* __restrict__ Bhi, const bf16* __restrict__ Blo,
    const float* __restrict__ bias, float* __restrict__ C,
    bf16* __restrict__ Chi, bf16* __restrict__ Clo,
    int N, int K)
{
    extern __shared__ bf16 smg[];

    const int tid  = threadIdx.x;
    const int warp = tid >> 5;
    const int lane = tid & 31;
    const int bm0  = blockIdx.y * 128;
    const int bn0  = blockIdx.x * 128;
    const int wm   = (warp & 1) * 64;
    const int wn   = (warp >> 1) * 32;

    float acc[4][4][4];
    #pragma unroll
    for (int mt = 0; mt < 4; mt++)
        #pragma unroll
        for (int nt = 0; nt < 4; nt++)
            #pragma unroll
            for (int i = 0; i < 4; i++) acc[mt][nt][i] = 0.f;

    const int a_r = lane & 15;
    const int a_c = (lane >> 4) * 8;
    const int b_r = lane & 7;
    const int b_c = ((lane >> 3) & 1) * 8;
    const int nch = K >> 5;

    gemm_issue(smg, Ahi, Alo, Bhi, Blo, bm0, bn0, K, 0, tid);
    CP_COMMIT();
    gemm_issue(smg + 4 * GSTG, Ahi, Alo, Bhi, Blo, bm0, bn0, K, 32, tid);
    CP_COMMIT();

    for (int ch = 0; ch < nch; ch++) {
        if (ch == nch - 1) { CP_WAIT(0); } else { CP_WAIT(1); }
        __syncthreads();
        if (ch + 2 < nch) {
            int st = (ch + 2) % 3;
            gemm_issue(smg + st * 4 * GSTG, Ahi, Alo, Bhi, Blo,
                       bm0, bn0, K, (ch + 2) << 5, tid);
            CP_COMMIT();
        }

        bf16* cur = smg + (ch % 3) * 4 * GSTG;
        bf16* AsH = cur;
        bf16* AsL = cur + GSTG;
        bf16* BsH = cur + 2 * GSTG;
        bf16* BsL = cur + 3 * GSTG;

        #pragma unroll
        for (int ks = 0; ks < 2; ks++) {
            uint32_t ah[4][4], al[4][4], bh[4][2], bl[4][2];
            #pragma unroll
            for (int mt = 0; mt < 4; mt++) {
                int r = wm + mt * 16 + a_r;
                int c = ks * 16 + a_c;
                ldsm4(ah[mt], smem_u32(&AsH[r * SMSTR + c]));
                ldsm4(al[mt], smem_u32(&AsL[r * SMSTR + c]));
            }
            #pragma unroll
            for (int nt = 0; nt < 4; nt++) {
                int r = wn + nt * 8 + b_r;
                int c = ks * 16 + b_c;
                ldsm2(bh[nt], smem_u32(&BsH[r * SMSTR + c]));
                ldsm2(bl[nt], smem_u32(&BsL[r * SMSTR + c]));
            }
            #pragma unroll
            for (int mt = 0; mt < 4; mt++)
                #pragma unroll
                for (int nt = 0; nt < 4; nt++) {
                    mma_bf16(acc[mt][nt], ah[mt], bh[nt]);
                    mma_bf16(acc[mt][nt], ah[mt], bl[nt]);
                    mma_bf16(acc[mt][nt], al[mt], bh[nt]);
                }
        }
    }

    #pragma unroll
    for (int mt = 0; mt < 4; mt++) {
        #pragma unroll
        for (int nt = 0; nt < 4; nt++) {
            int row = bm0 + wm + mt * 16 + (lane >> 2);
            int col = bn0 + wn + nt * 8 + (lane & 3) * 2;
            float bv0 = bias[col], bv1 = bias[col + 1];
            float v0 = acc[mt][nt][0] + bv0;
            float v1 = acc[mt][nt][1] + bv1;
            float v2 = acc[mt][nt][2] + bv0;
            float v3 = acc[mt][nt][3] + bv1;
            if (RELU) {
                v0 = fmaxf(v0, 0.f); v1 = fmaxf(v1, 0.f);
                v2 = fmaxf(v2, 0.f); v3 = fmaxf(v3, 0.f);
            }
            if (SPLIT) {
                size_t o0 = (size_t)row * N + col;
                size_t o1 = (size_t)(row + 8) * N + col;
                uint32_t h01 = pk2f(v0, v1);
                uint32_t h23 = pk2f(v2, v3);
                *(uint32_t*)&Chi[o0] = h01;
                *(uint32_t*)&Chi[o1] = h23;
                *(uint32_t*)&Clo[o0] = pk2f(v0 - __uint_as_float(h01 << 16),
                                            v1 - __uint_as_float(h01 & 0xFFFF0000u));
                *(uint32_t*)&Clo[o1] = pk2f(v2 - __uint_as_float(h23 << 16),
                                            v3 - __uint_as_float(h23 & 0xFFFF0000u));
            } else {
                *(float2*)&C[(size_t)row * N + col]       = make_float2(v0, v1);
                *(float2*)&C[(size_t)(row + 8) * N + col] = make_float2(v2, v3);
            }
        }
    }
}

// ---------------- 3-stage split-bf16 flash attention (K == V) ----------------
#define ASTR 72
#define QELT (128 * ASTR)
#define KELT (64 * ASTR)

__device__ __forceinline__ void attn_issueK(
    bf16* KsH, bf16* KsL, const bf16* KVhi, const bf16* KVlo,
    int t0, int h, int tid)
{
    #pragma unroll
    for (int t = 0; t < 2; t++) {
        int i = tid + t * 256;
        int row = i >> 3, seg = (i & 7) * 8;
        size_t g = (size_t)(t0 + row) * D_DIM + h * 64 + seg;
        cp16(smem_u32(KsH + row * ASTR + seg), KVhi + g);
        cp16(smem_u32(KsL + row * ASTR + seg), KVlo + g);
    }
}

template<bool CAUSAL>
__global__ void __launch_bounds__(256, 1) mm_attn(
    const bf16* __restrict__ Qhi, const bf16* __restrict__ Qlo,
    const bf16* __restrict__ KVhi, const bf16* __restrict__ KVlo,
    float* __restrict__ Out)
{
    extern __shared__ bf16 smA[];
    bf16* QsH = smA;
    bf16* QsL = smA + QELT;
    bf16* Kst = smA + 2 * QELT;    // 3 stages x (KsH, KsL)

    int h, q0;
    if (CAUSAL) {
        // LPT: heaviest q-blocks (largest q0) dispatch first
        h  = blockIdx.x & (H_HEADS - 1);
        q0 = (S_LEN / 128 - 1 - (blockIdx.x >> 4)) * 128;
    } else {
        h  = blockIdx.y;
        q0 = blockIdx.x * 128;
    }
    const int tid = threadIdx.x;
    const int warp = tid >> 5;
    const int lane = tid & 31;
    const int wr  = warp * 16;

    const int ntiles = CAUSAL ? (q0 / 64 + 2) : (S_LEN / 64);

    // prologue: Q + K0 (group A), K1 (group B)
    #pragma unroll
    for (int t = 0; t < 4; t++) {
        int i = tid + t * 256;
        int row = i >> 3, seg = (i & 7) * 8;
        size_t g = (size_t)(q0 + row) * D_DIM + h * 64 + seg;
        cp16(smem_u32(QsH + row * ASTR + seg), Qhi + g);
        cp16(smem_u32(QsL + row * ASTR + seg), Qlo + g);
    }
    attn_issueK(Kst, Kst + KELT, KVhi, KVlo, 0, h, tid);
    CP_COMMIT();
    attn_issueK(Kst + 2 * KELT, Kst + 3 * KELT, KVhi, KVlo, 64, h, tid);
    CP_COMMIT();

    float m0 = -1e30f, m1 = -1e30f, l0 = 0.f, l1 = 0.f;
    float o[8][4];
    #pragma unroll
    for (int dn = 0; dn < 8; dn++)
        #pragma unroll
        for (int i = 0; i < 4; i++) o[dn][i] = 0.f;

    const int r0 = q0 + wr + (lane >> 2);

    for (int kt = 0; kt < ntiles; kt++) {
        const int t0 = kt * 64;
        if (kt == ntiles - 1) { CP_WAIT(0); } else { CP_WAIT(1); }
        __syncthreads();
        if (kt + 2 < ntiles) {
            bf16* nH = Kst + ((kt + 2) % 3) * 2 * KELT;
            attn_issueK(nH, nH + KELT, KVhi, KVlo, (kt + 2) * 64, h, tid);
            CP_COMMIT();
        }
        bf16* KsH = Kst + (kt % 3) * 2 * KELT;
        bf16* KsL = KsH + KELT;

        // ---- S = Q K^T ----
        float s[8][4];
        #pragma unroll
        for (int nt = 0; nt < 8; nt++)
            #pragma unroll
            for (int i = 0; i < 4; i++) s[nt][i] = 0.f;

        #pragma unroll
        for (int ks = 0; ks < 4; ks++) {
            uint32_t ah[4], al[4];
            int ac = ks * 16 + (lane >> 4) * 8;
            ldsm4(ah, smem_u32(&QsH[(wr + (lane & 15)) * ASTR + ac]));
            ldsm4(al, smem_u32(&QsL[(wr + (lane & 15)) * ASTR + ac]));
            #pragma unroll
            for (int nt = 0; nt < 8; nt++) {
                uint32_t bh[2], bl[2];
                int br = nt * 8 + (lane & 7);
                int bc = ks * 16 + ((lane >> 3) & 1) * 8;
                ldsm2(bh, smem_u32(&KsH[br * ASTR + bc]));
                ldsm2(bl, smem_u32(&KsL[br * ASTR + bc]));
                mma_bf16(s[nt], ah, bh);
                mma_bf16(s[nt], ah, bl);
                mma_bf16(s[nt], al, bh);
            }
        }

        // ---- scale + mask + online softmax ----
        float mx0 = -1e30f, mx1 = -1e30f;
        #pragma unroll
        for (int nt = 0; nt < 8; nt++) {
            #pragma unroll
            for (int i = 0; i < 4; i++) s[nt][i] *= 0.125f;
            if (CAUSAL && kt >= ntiles - 2) {
                int col = t0 + nt * 8 + (lane & 3) * 2;
                if (col     > r0)     s[nt][0] = -1e9f;
                if (col + 1 > r0)     s[nt][1] = -1e9f;
                if (col     > r0 + 8) s[nt][2] = -1e9f;
                if (col + 1 > r0 + 8) s[nt][3] = -1e9f;
            }
            mx0 = fmaxf(mx0, fmaxf(s[nt][0], s[nt][1]));
            mx1 = fmaxf(mx1, fmaxf(s[nt][2], s[nt][3]));
        }
        mx0 = fmaxf(mx0, __shfl_xor_sync(0xffffffffu, mx0, 1));
        mx0 = fmaxf(mx0, __shfl_xor_sync(0xffffffffu, mx0, 2));
        mx1 = fmaxf(mx1, __shfl_xor_sync(0xffffffffu, mx1, 1));
        mx1 = fmaxf(mx1, __shfl_xor_sync(0xffffffffu, mx1, 2));

        float mn0 = fmaxf(m0, mx0), mn1 = fmaxf(m1, mx1);
        float al0 = __expf(m0 - mn0), al1 = __expf(m1 - mn1);
        float ls0 = 0.f, ls1 = 0.f;
        #pragma unroll
        for (int nt = 0; nt < 8; nt++) {
            s[nt][0] = __expf(s[nt][0] - mn0);
            s[nt][1] = __expf(s[nt][1] - mn0);
            s[nt][2] = __expf(s[nt][2] - mn1);
            s[nt][3] = __expf(s[nt][3] - mn1);
            ls0 += s[nt][0] + s[nt][1];
            ls1 += s[nt][2] + s[nt][3];
        }
        ls0 += __shfl_xor_sync(0xffffffffu, ls0, 1);
        ls0 += __shfl_xor_sync(0xffffffffu, ls0, 2);
        ls1 += __shfl_xor_sync(0xffffffffu, ls1, 1);
        ls1 += __shfl_xor_sync(0xffffffffu, ls1, 2);
        l0 = l0 * al0 + ls0;
        l1 = l1 * al1 + ls1;
        m0 = mn0; m1 = mn1;
        #pragma unroll
        for (int dn = 0; dn < 8; dn++) {
            o[dn][0] *= al0; o[dn][1] *= al0;
            o[dn][2] *= al1; o[dn][3] *= al1;
        }

        // ---- O += P V  (V == K, transposed reads); packed bf16x2 repack ----
        #pragma unroll
        for (int kc = 0; kc < 4; kc++) {
            uint32_t pa_h[4], pa_l[4];
            {
                const float* p0 = s[2 * kc];
                const float* p1 = s[2 * kc + 1];
                pa_h[0] = pk2f(p0[0], p0[1]);
                pa_h[1] = pk2f(p0[2], p0[3]);
                pa_h[2] = pk2f(p1[0], p1[1]);
                pa_h[3] = pk2f(p1[2], p1[3]);
                pa_l[0] = pk2f(p0[0] - __uint_as_float(pa_h[0] << 16),
                               p0[1] - __uint_as_float(pa_h[0] & 0xFFFF0000u));
                pa_l[1] = pk2f(p0[2] - __uint_as_float(pa_h[1] << 16),
                               p0[3] - __uint_as_float(pa_h[1] & 0xFFFF0000u));
                pa_l[2] = pk2f(p1[0] - __uint_as_float(pa_h[2] << 16),
                               p1[1] - __uint_as_float(pa_h[2] & 0xFFFF0000u));
                pa_l[3] = pk2f(p1[2] - __uint_as_float(pa_h[3] << 16),
                               p1[3] - __uint_as_float(pa_h[3] & 0xFFFF0000u));
            }
            int vr = kc * 16 + (lane & 15);
            #pragma unroll
            for (int dn = 0; dn < 8; dn++) {
                uint32_t bh[2], bl[2];
                ldsm2t(bh, smem_u32(&KsH[vr * ASTR + dn * 8]));
                ldsm2t(bl, smem_u32(&KsL[vr * ASTR + dn * 8]));
                mma_bf16(o[dn], pa_h, bh);
                mma_bf16(o[dn], pa_h, bl);
                mma_bf16(o[dn], pa_l, bh);
            }
        }
    }

    float inv0 = 1.f / l0, inv1 = 1.f / l1;
    #pragma unroll
    for (int dn = 0; dn < 8; dn++) {
        int col = h * 64 + dn * 8 + (lane & 3) * 2;
        *(float2*)&Out[(size_t)r0 * D_DIM + col] =
            make_float2(o[dn][0] * inv0, o[dn][1] * inv0);
        *(float2*)&Out[(size_t)(r0 + 8) * D_DIM + col] =
            make_float2(o[dn][2] * inv1, o[dn][3] * inv1);
    }
}

// ---------------- activation fp32 -> bf16 hi/lo split ----------------
__global__ void cvt_act(const float4* __restrict__ x, uint2* __restrict__ hi,
                        uint2* __restrict__ lo, int n4) {
    int i = blockIdx.x * 256 + threadIdx.x;
    if (i >= n4) return;
    float4 v = x[i];
    uint32_t h01 = pk2f(v.x, v.y);
    uint32_t h23 = pk2f(v.z, v.w);
    uint32_t l01 = pk2f(v.x - __uint_as_float(h01 << 16),
                        v.y - __uint_as_float(h01 & 0xFFFF0000u));
    uint32_t l23 = pk2f(v.z - __uint_as_float(h23 << 16),
                        v.w - __uint_as_float(h23 & 0xFFFF0000u));
    hi[i] = make_uint2(h01, h23);
    lo[i] = make_uint2(l01, l23);
}

// ---------------- weight prep ----------------
__global__ void prep_projW(const float* __restrict__ W, bf16* __restrict__ hi,
                           bf16* __restrict__ lo) {
    int idx = blockIdx.x * 256 + threadIdx.x;
    int k = idx & 1023, n = idx >> 10;
    int h = n >> 6, e = n & 63;
    float v = W[(h << 16) + (k << 6) + e];
    bf16 hv = __float2bfloat16(v);
    hi[idx] = hv;
    lo[idx] = __float2bfloat16(v - __bfloat162float(hv));
}

__global__ void prep_T(const float* __restrict__ in, bf16* __restrict__ hi,
                       bf16* __restrict__ lo, int R, int C) {
    __shared__ float t[32][33];
    int bx = blockIdx.x * 32, by = blockIdx.y * 32;
    int tx = threadIdx.x, ty = threadIdx.y;
    #pragma unroll
    for (int i = 0; i < 32; i += 8)
        t[ty + i][tx] = in[(size_t)(by + ty + i) * C + bx + tx];
    __syncthreads();
    #pragma unroll
    for (int i = 0; i < 32; i += 8) {
        float v = t[tx][ty + i];
        bf16 hv = __float2bfloat16(v);
        size_t o = (size_t)(bx + ty + i) * R + by + tx;
        hi[o] = hv;
        lo[o] = __float2bfloat16(v - __bfloat162float(hv));
    }
}

// ---------------- fused residual add + LayerNorm (+optional hi/lo split out) ----------------
__device__ __forceinline__ float warpReduceSum(float v) {
    #pragma unroll
    for (int off = 16; off > 0; off >>= 1)
        v += __shfl_xor_sync(0xffffffffu, v, off);
    return v;
}
__device__ __forceinline__ float blockReduceSum(float v, float* sh) {
    int lane = threadIdx.x & 31, w = threadIdx.x >> 5;
    __syncthreads();
    v = warpReduceSum(v);
    if (lane == 0) sh[w] = v;
    __syncthreads();
    if (w == 0) {
        float t = (lane < 8) ? sh[lane] : 0.f;
        t = warpReduceSum(t);
        if (lane == 0) sh[0] = t;
    }
    __syncthreads();
    return sh[0];
}

template<bool SPLIT>
__global__ void add_ln_kernel(const float* __restrict__ A, const float* __restrict__ Bv,
                              const float* __restrict__ g, const float* __restrict__ beta,
                              float* __restrict__ out,
                              bf16* __restrict__ hi, bf16* __restrict__ lo) {
    __shared__ float red[8];
    const int row = blockIdx.x;
    const int tid = threadIdx.x;
    float x[4];
    float s = 0.f;
    #pragma unroll
    for (int i = 0; i < 4; i++) {
        int c = tid + i * 256;
        x[i] = A[(size_t)row * D_DIM + c] + Bv[(size_t)row * D_DIM + c];
        s += x[i];
    }
    s = blockReduceSum(s, red);
    const float mu = s * (1.f / D_DIM);
    float v = 0.f;
    #pragma unroll
    for (int i = 0; i < 4; i++) { float d = x[i] - mu; v += d * d; }
    v = blockReduceSum(v, red);
    const float rstd = rsqrtf(v * (1.f / D_DIM) + 1e-5f);
    #pragma unroll
    for (int i = 0; i < 4; i++) {
        int c = tid + i * 256;
        float r = (x[i] - mu) * rstd * g[c] + beta[c];
        out[(size_t)row * D_DIM + c] = r;
        if (SPLIT) {
            bf16 hv = __float2bfloat16(r);
            hi[(size_t)row * D_DIM + c] = hv;
            lo[(size_t)row * D_DIM + c] = __float2bfloat16(r - __bfloat162float(hv));
        }
    }
}

// ---------------- launch ----------------
extern "C" void kernel_launch(void* const* d_in, const int* in_sizes, int n_in,
                              void* d_out, int out_size) {
    const float* y   = (const float*)d_in[0];
    const float* enc = (const float*)d_in[1];
    const float* WqS = (const float*)d_in[2];
    const float* bqS = (const float*)d_in[3];
    const float* WqC = (const float*)d_in[4];
    const float* bqC = (const float*)d_in[5];
    const float* g1  = (const float*)d_in[6];
    const float* be1 = (const float*)d_in[7];
    const float* g2  = (const float*)d_in[8];
    const float* be2 = (const float*)d_in[9];
    const float* g3  = (const float*)d_in[10];
    const float* be3 = (const float*)d_in[11];
    const float* w1  = (const float*)d_in[12];
    const float* b1  = (const float*)d_in[13];
    const float* w2  = (const float*)d_in[14];
    const float* b2  = (const float*)d_in[15];
    float* outp = (float*)d_out;

    float *AO, *y1, *y2, *FF;
    bf16 *Phi, *Plo, *CatHi, *CatLo, *QKhi, *QKlo, *Hhi, *Hlo, *Ahi, *Alo;
    bf16 *BtS_hi, *BtS_lo, *BtC_hi, *BtC_lo, *Bt1_hi, *Bt1_lo, *Bt2_hi, *Bt2_lo;
    cudaGetSymbolAddress((void**)&AO, g_AO);
    cudaGetSymbolAddress((void**)&y1, g_y1);
    cudaGetSymbolAddress((void**)&y2, g_y2);
    cudaGetSymbolAddress((void**)&FF, g_FF);
    cudaGetSymbolAddress((void**)&Phi,   g_Phi);
    cudaGetSymbolAddress((void**)&Plo,   g_Plo);
    cudaGetSymbolAddress((void**)&CatHi, g_Cat_hi);
    cudaGetSymbolAddress((void**)&CatLo, g_Cat_lo);
    cudaGetSymbolAddress((void**)&QKhi,  g_QK_hi);
    cudaGetSymbolAddress((void**)&QKlo,  g_QK_lo);
    cudaGetSymbolAddress((void**)&Hhi,   g_Hhi);
    cudaGetSymbolAddress((void**)&Hlo,   g_Hlo);
    cudaGetSymbolAddress((void**)&Ahi,   g_Ahi);
    cudaGetSymbolAddress((void**)&Alo,   g_Alo);
    cudaGetSymbolAddress((void**)&BtS_hi, g_BtS_hi);
    cudaGetSymbolAddress((void**)&BtS_lo, g_BtS_lo);
    cudaGetSymbolAddress((void**)&BtC_hi, g_BtC_hi);
    cudaGetSymbolAddress((void**)&BtC_lo, g_BtC_lo);
    cudaGetSymbolAddress((void**)&Bt1_hi, g_Bt1_hi);
    cudaGetSymbolAddress((void**)&Bt1_lo, g_Bt1_lo);
    cudaGetSymbolAddress((void**)&Bt2_hi, g_Bt2_hi);
    cudaGetSymbolAddress((void**)&Bt2_lo, g_Bt2_lo);

    const int GEMM_SMEM = 3 * 4 * GSTG * 2;            // 122880 B
    const int ATT_SMEM  = (2 * QELT + 6 * KELT) * 2;   // 92160 B
    cudaFuncSetAttribute(mm_gemm<false, true>,  cudaFuncAttributeMaxDynamicSharedMemorySize, GEMM_SMEM);
    cudaFuncSetAttribute(mm_gemm<true, true>,   cudaFuncAttributeMaxDynamicSharedMemorySize, GEMM_SMEM);
    cudaFuncSetAttribute(mm_gemm<false, false>, cudaFuncAttributeMaxDynamicSharedMemorySize, GEMM_SMEM);
    cudaFuncSetAttribute(mm_attn<true>,  cudaFuncAttributeMaxDynamicSharedMemorySize, ATT_SMEM);
    cudaFuncSetAttribute(mm_attn<false>, cudaFuncAttributeMaxDynamicSharedMemorySize, ATT_SMEM);

    // weight prep
    prep_projW<<<(D_DIM * D_DIM) / 256, 256>>>(WqS, BtS_hi, BtS_lo);
    prep_projW<<<(D_DIM * D_DIM) / 256, 256>>>(WqC, BtC_hi, BtC_lo);
    prep_T<<<dim3(HID_DIM / 32, D_DIM / 32), dim3(32, 8)>>>(w1, Bt1_hi, Bt1_lo, D_DIM, HID_DIM);
    prep_T<<<dim3(D_DIM / 32, HID_DIM / 32), dim3(32, 8)>>>(w2, Bt2_hi, Bt2_lo, HID_DIM, D_DIM);

    const int N_SD = S_LEN * D_DIM;

    // convert inputs: y -> A, enc -> Cat second half
    cvt_act<<<N_SD / 4 / 256, 256>>>((const float4*)y, (uint2*)Ahi, (uint2*)Alo, N_SD / 4);
    cvt_act<<<N_SD / 4 / 256, 256>>>((const float4*)enc,
        (uint2*)(CatHi + N_SD), (uint2*)(CatLo + N_SD), N_SD / 4);

    // P (hi/lo) = y @ WtS + bqS
    mm_gemm<false, true><<<dim3(D_DIM / 128, S_LEN / 128), 256, GEMM_SMEM>>>(
        Ahi, Alo, BtS_hi, BtS_lo, bqS, nullptr, Phi, Plo, D_DIM, D_DIM);

    // self attention (q=k=v=P), causal — flattened LPT grid
    mm_attn<true><<<dim3((S_LEN / 128) * H_HEADS), 256, ATT_SMEM>>>(Phi, Plo, Phi, Plo, AO);
    // y1 = LN(y + AO), also split into Cat first half
    add_ln_kernel<true><<<S_LEN, 256>>>(y, AO, g1, be1, y1, CatHi, CatLo);

    // [Qc ; Kc] = [y1 ; enc] @ WtC + bqC   (one combined GEMM, M = 4096)
    mm_gemm<false, true><<<dim3(D_DIM / 128, 2 * S_LEN / 128), 256, GEMM_SMEM>>>(
        CatHi, CatLo, BtC_hi, BtC_lo, bqC, nullptr, QKhi, QKlo, D_DIM, D_DIM);

    // cross attention (k=v), non-causal
    mm_attn<false><<<dim3(S_LEN / 128, H_HEADS), 256, ATT_SMEM>>>(
        QKhi, QKlo, QKhi + N_SD, QKlo + N_SD, AO);
    // y2 = LN(y1 + AO), split into A
    add_ln_kernel<true><<<S_LEN, 256>>>(y1, AO, g2, be2, y2, Ahi, Alo);

    // Hd (hi/lo) = relu(y2 @ w1 + b1)
    mm_gemm<true, true><<<dim3(HID_DIM / 128, S_LEN / 128), 256, GEMM_SMEM>>>(
        Ahi, Alo, Bt1_hi, Bt1_lo, b1, nullptr, Hhi, Hlo, HID_DIM, D_DIM);

    // FF = Hd @ w2 + b2 (fp32)
    mm_gemm<false, false><<<dim3(D_DIM / 128, S_LEN / 128), 256, GEMM_SMEM>>>(
        Hhi, Hlo, Bt2_hi, Bt2_lo, b2, FF, nullptr, nullptr, D_DIM, HID_DIM);

    // out = LN(y2 + FF)
    add_ln_kernel<false><<<S_LEN, 256>>>(y2, FF, g3, be3, outp, nullptr, nullptr);
}

// round 15
// speedup vs baseline: 3.1238x; 1.0579x over previous
#include <cuda_runtime.h>
#include <cuda_bf16.h>
#include <cstdint>

#define S_LEN 2048
#define D_DIM 1024
#define H_HEADS 16
#define DH_DIM 64
#define HID_DIM 4096

typedef __nv_bfloat16 bf16;

// ---------------- static scratch ----------------
__device__ float g_AO [S_LEN * D_DIM];
__device__ float g_y1 [S_LEN * D_DIM];
__device__ float g_y2 [S_LEN * D_DIM];
__device__ float g_FF [S_LEN * D_DIM];

__device__ bf16 g_Phi [S_LEN * D_DIM];
__device__ bf16 g_Plo [S_LEN * D_DIM];
__device__ bf16 g_Cat_hi[2 * S_LEN * D_DIM];   // [y1 ; enc] stacked
__device__ bf16 g_Cat_lo[2 * S_LEN * D_DIM];
__device__ bf16 g_QK_hi [2 * S_LEN * D_DIM];   // [Qc ; Kc] stacked
__device__ bf16 g_QK_lo [2 * S_LEN * D_DIM];
__device__ bf16 g_Hhi [S_LEN * HID_DIM];
__device__ bf16 g_Hlo [S_LEN * HID_DIM];
__device__ bf16 g_Ahi [S_LEN * D_DIM];
__device__ bf16 g_Alo [S_LEN * D_DIM];

__device__ bf16 g_BtS_hi[D_DIM * D_DIM];
__device__ bf16 g_BtS_lo[D_DIM * D_DIM];
__device__ bf16 g_BtC_hi[D_DIM * D_DIM];
__device__ bf16 g_BtC_lo[D_DIM * D_DIM];
__device__ bf16 g_Bt1_hi[HID_DIM * D_DIM];
__device__ bf16 g_Bt1_lo[HID_DIM * D_DIM];
__device__ bf16 g_Bt2_hi[D_DIM * HID_DIM];
__device__ bf16 g_Bt2_lo[D_DIM * HID_DIM];

// ---------------- helpers ----------------
__device__ __forceinline__ uint32_t smem_u32(const void* p) {
    uint32_t a;
    asm("{ .reg .u64 t; cvta.to.shared.u64 t, %1; cvt.u32.u64 %0, t; }" : "=r"(a) : "l"(p));
    return a;
}
// packed convert: a -> low half, b -> high half (rn rounding)
__device__ __forceinline__ uint32_t pk2f(float a, float b) {
    uint32_t r;
    asm("cvt.rn.bf16x2.f32 %0, %1, %2;" : "=r"(r) : "f"(b), "f"(a));
    return r;
}
__device__ __forceinline__ void cp16(uint32_t dst, const void* src) {
    asm volatile("cp.async.cg.shared.global [%0], [%1], 16;" :: "r"(dst), "l"(src));
}
#define CP_COMMIT() asm volatile("cp.async.commit_group;" ::: "memory")
#define CP_WAIT(N)  asm volatile("cp.async.wait_group %0;" :: "n"(N) : "memory")
__device__ __forceinline__ void ldsm4(uint32_t r[4], uint32_t addr) {
    asm volatile("ldmatrix.sync.aligned.m8n8.x4.shared.b16 {%0,%1,%2,%3}, [%4];"
        : "=r"(r[0]), "=r"(r[1]), "=r"(r[2]), "=r"(r[3]) : "r"(addr));
}
__device__ __forceinline__ void ldsm4t(uint32_t r[4], uint32_t addr) {
    asm volatile("ldmatrix.sync.aligned.m8n8.x4.trans.shared.b16 {%0,%1,%2,%3}, [%4];"
        : "=r"(r[0]), "=r"(r[1]), "=r"(r[2]), "=r"(r[3]) : "r"(addr));
}
__device__ __forceinline__ void mma_bf16(float d[4], const uint32_t a[4], const uint32_t b[2]) {
    asm volatile(
        "mma.sync.aligned.m16n8k16.row.col.f32.bf16.bf16.f32 "
        "{%0,%1,%2,%3}, {%4,%5,%6,%7}, {%8,%9}, {%0,%1,%2,%3};"
        : "+f"(d[0]), "+f"(d[1]), "+f"(d[2]), "+f"(d[3])
        : "r"(a[0]), "r"(a[1]), "r"(a[2]), "r"(a[3]), "r"(b[0]), "r"(b[1]));
}
__device__ __forceinline__ void mma_pair(float d[4], const uint32_t a[4], const uint32_t b4[4], int sel) {
    const uint32_t b[2] = { b4[sel * 2], b4[sel * 2 + 1] };
    mma_bf16(d, a, b);
}

// ---------------- 3-stage split-bf16 mma.sync GEMM ----------------
#define SMSTR 40
#define GSTG (128 * SMSTR)   // elements per array per stage

__device__ __forceinline__ void gemm_issue(
    bf16* base, const bf16* Ahi, const bf16* Alo, const bf16* Bhi, const bf16* Blo,
    int bm0, int bn0, int K, int k0, int tid)
{
    #pragma unroll
    for (int t = 0; t < 2; t++) {
        int i = tid + t * 256;
        int row = i >> 2, seg = (i & 3) * 8;
        size_t ga = (size_t)(bm0 + row) * K + k0 + seg;
        size_t gb = (size_t)(bn0 + row) * K + k0 + seg;
        int so = row * SMSTR + seg;
        cp16(smem_u32(base + so),            Ahi + ga);
        cp16(smem_u32(base + GSTG + so),     Alo + ga);
        cp16(smem_u32(base + 2 * GSTG + so), Bhi + gb);
        cp16(smem_u32(base + 3 * GSTG + so), Blo + gb);
    }
}

template<bool RELU, bool SPLIT>
__global__ void __launch_bounds__(256, 1) mm_gemm(
    const bf16* __restrict__ Ahi, const bf16* __restrict__ Alo,
    const bf16* __restrict__ Bhi, const bf16* __restrict__ Blo,
    const float* __restrict__ bias, float* __restrict__ C,
    bf16* __restrict__ Chi, bf16* __restrict__ Clo,
    int N, int K)
{
    extern __shared__ bf16 smg[];

    const int tid  = threadIdx.x;
    const int warp = tid >> 5;
    const int lane = tid & 31;
    const int bm0  = blockIdx.y * 128;
    const int bn0  = blockIdx.x * 128;
    const int wm   = (warp & 1) * 64;
    const int wn   = (warp >> 1) * 32;

    float acc[4][4][4];
    #pragma unroll
    for (int mt = 0; mt < 4; mt++)
        #pragma unroll
        for (int nt = 0; nt < 4; nt++)
            #pragma unroll
            for (int i = 0; i < 4; i++) acc[mt][nt][i] = 0.f;

    const int a_r = lane & 15;
    const int a_c = (lane >> 4) * 8;
    const int bx_r = ((lane >> 4) & 1) * 8 + (lane & 7);   // x4 B row-in-pair
    const int bx_c = ((lane >> 3) & 1) * 8;                // x4 B col (k half)
    const int nch = K >> 5;

    gemm_issue(smg, Ahi, Alo, Bhi, Blo, bm0, bn0, K, 0, tid);
    CP_COMMIT();
    gemm_issue(smg + 4 * GSTG, Ahi, Alo, Bhi, Blo, bm0, bn0, K, 32, tid);
    CP_COMMIT();

    for (int ch = 0; ch < nch; ch++) {
        if (ch == nch - 1) { CP_WAIT(0); } else { CP_WAIT(1); }
        __syncthreads();
        if (ch + 2 < nch) {
            int st = (ch + 2) % 3;
            gemm_issue(smg + st * 4 * GSTG, Ahi, Alo, Bhi, Blo,
                       bm0, bn0, K, (ch + 2) << 5, tid);
            CP_COMMIT();
        }

        bf16* cur = smg + (ch % 3) * 4 * GSTG;
        bf16* AsH = cur;
        bf16* AsL = cur + GSTG;
        bf16* BsH = cur + 2 * GSTG;
        bf16* BsL = cur + 3 * GSTG;

        #pragma unroll
        for (int ks = 0; ks < 2; ks++) {
            uint32_t ah[4][4], al[4][4], bh4[2][4], bl4[2][4];
            #pragma unroll
            for (int mt = 0; mt < 4; mt++) {
                int r = wm + mt * 16 + a_r;
                int c = ks * 16 + a_c;
                ldsm4(ah[mt], smem_u32(&AsH[r * SMSTR + c]));
                ldsm4(al[mt], smem_u32(&AsL[r * SMSTR + c]));
            }
            #pragma unroll
            for (int ntp = 0; ntp < 2; ntp++) {
                int r = wn + ntp * 16 + bx_r;
                int c = ks * 16 + bx_c;
                ldsm4(bh4[ntp], smem_u32(&BsH[r * SMSTR + c]));
                ldsm4(bl4[ntp], smem_u32(&BsL[r * SMSTR + c]));
            }
            #pragma unroll
            for (int mt = 0; mt < 4; mt++)
                #pragma unroll
                for (int nt = 0; nt < 4; nt++) {
                    mma_pair(acc[mt][nt], ah[mt], bh4[nt >> 1], nt & 1);
                    mma_pair(acc[mt][nt], ah[mt], bl4[nt >> 1], nt & 1);
                    mma_pair(acc[mt][nt], al[mt], bh4[nt >> 1], nt & 1);
                }
        }
    }

    #pragma unroll
    for (int mt = 0; mt < 4; mt++) {
        #pragma unroll
        for (int nt = 0; nt < 4; nt++) {
            int row = bm0 + wm + mt * 16 + (lane >> 2);
            int col = bn0 + wn + nt * 8 + (lane & 3) * 2;
            float bv0 = bias[col], bv1 = bias[col + 1];
            float v0 = acc[mt][nt][0] + bv0;
            float v1 = acc[mt][nt][1] + bv1;
            float v2 = acc[mt][nt][2] + bv0;
            float v3 = acc[mt][nt][3] + bv1;
            if (RELU) {
                v0 = fmaxf(v0, 0.f); v1 = fmaxf(v1, 0.f);
                v2 = fmaxf(v2, 0.f); v3 = fmaxf(v3, 0.f);
            }
            if (SPLIT) {
                size_t o0 = (size_t)row * N + col;
                size_t o1 = (size_t)(row + 8) * N + col;
                uint32_t h01 = pk2f(v0, v1);
                uint32_t h23 = pk2f(v2, v3);
                *(uint32_t*)&Chi[o0] = h01;
                *(uint32_t*)&Chi[o1] = h23;
                *(uint32_t*)&Clo[o0] = pk2f(v0 - __uint_as_float(h01 << 16),
                                            v1 - __uint_as_float(h01 & 0xFFFF0000u));
                *(uint32_t*)&Clo[o1] = pk2f(v2 - __uint_as_float(h23 << 16),
                                            v3 - __uint_as_float(h23 & 0xFFFF0000u));
            } else {
                *(float2*)&C[(size_t)row * N + col]       = make_float2(v0, v1);
                *(float2*)&C[(size_t)(row + 8) * N + col] = make_float2(v2, v3);
            }
        }
    }
}

// ---------------- 3-stage split-bf16 flash attention (K == V) ----------------
// NMT = q-rows per warp / 16 (1 -> 128-row CTA tile, 2 -> 256-row CTA tile)
#define ASTR 72
#define KELT (64 * ASTR)

__device__ __forceinline__ void attn_issueK(
    bf16* KsH, bf16* KsL, const bf16* KVhi, const bf16* KVlo,
    int t0, int h, int tid)
{
    #pragma unroll
    for (int t = 0; t < 2; t++) {
        int i = tid + t * 256;
        int row = i >> 3, seg = (i & 7) * 8;
        size_t g = (size_t)(t0 + row) * D_DIM + h * 64 + seg;
        cp16(smem_u32(KsH + row * ASTR + seg), KVhi + g);
        cp16(smem_u32(KsL + row * ASTR + seg), KVlo + g);
    }
}

template<bool CAUSAL, int NMT>
__global__ void __launch_bounds__(256, 1) mm_attn(
    const bf16* __restrict__ Qhi, const bf16* __restrict__ Qlo,
    const bf16* __restrict__ KVhi, const bf16* __restrict__ KVlo,
    float* __restrict__ Out)
{
    constexpr int QROWS = NMT * 128;
    constexpr int QE = QROWS * ASTR;
    extern __shared__ bf16 smA[];
    bf16* QsH = smA;
    bf16* QsL = smA + QE;
    bf16* Kst = smA + 2 * QE;    // 3 stages x (KsH, KsL)

    int h, q0;
    if (CAUSAL) {
        // LPT: heaviest q-blocks dispatch first (NMT==1 launch)
        h  = blockIdx.x & (H_HEADS - 1);
        q0 = (S_LEN / QROWS - 1 - (int)(blockIdx.x >> 4)) * QROWS;
    } else {
        h  = blockIdx.y;
        q0 = blockIdx.x * QROWS;
    }
    const int tid = threadIdx.x;
    const int warp = tid >> 5;
    const int lane = tid & 31;
    const int wr  = warp * (16 * NMT);

    const int ntiles = CAUSAL ? (q0 / 64 + 2 * NMT) : (S_LEN / 64);

    // prologue: Q + K0 (group A), K1 (group B)
    #pragma unroll
    for (int t = 0; t < 4 * NMT; t++) {
        int i = tid + t * 256;
        int row = i >> 3, seg = (i & 7) * 8;
        size_t g = (size_t)(q0 + row) * D_DIM + h * 64 + seg;
        cp16(smem_u32(QsH + row * ASTR + seg), Qhi + g);
        cp16(smem_u32(QsL + row * ASTR + seg), Qlo + g);
    }
    attn_issueK(Kst, Kst + KELT, KVhi, KVlo, 0, h, tid);
    CP_COMMIT();
    attn_issueK(Kst + 2 * KELT, Kst + 3 * KELT, KVhi, KVlo, 64, h, tid);
    CP_COMMIT();

    float m[NMT][2], l[NMT][2];
    float o[NMT][8][4];
    #pragma unroll
    for (int mt = 0; mt < NMT; mt++) {
        m[mt][0] = -1e30f; m[mt][1] = -1e30f;
        l[mt][0] = 0.f;    l[mt][1] = 0.f;
        #pragma unroll
        for (int dn = 0; dn < 8; dn++)
            #pragma unroll
            for (int i = 0; i < 4; i++) o[mt][dn][i] = 0.f;
    }

    const int bx_r = ((lane >> 4) & 1) * 8 + (lane & 7);
    const int bx_c = ((lane >> 3) & 1) * 8;
    const int vx_r = ((lane >> 3) & 1) * 8 + (lane & 7);
    const int vx_c = ((lane >> 4) & 1) * 8;

    for (int kt = 0; kt < ntiles; kt++) {
        const int t0 = kt * 64;
        if (kt == ntiles - 1) { CP_WAIT(0); } else { CP_WAIT(1); }
        __syncthreads();
        if (kt + 2 < ntiles) {
            bf16* nH = Kst + ((kt + 2) % 3) * 2 * KELT;
            attn_issueK(nH, nH + KELT, KVhi, KVlo, (kt + 2) * 64, h, tid);
            CP_COMMIT();
        }
        bf16* KsH = Kst + (kt % 3) * 2 * KELT;
        bf16* KsL = KsH + KELT;

        // ---- S = Q K^T ----
        float s[NMT][8][4];
        #pragma unroll
        for (int mt = 0; mt < NMT; mt++)
            #pragma unroll
            for (int nt = 0; nt < 8; nt++)
                #pragma unroll
                for (int i = 0; i < 4; i++) s[mt][nt][i] = 0.f;

        #pragma unroll
        for (int ks = 0; ks < 4; ks++) {
            uint32_t bh4[4][4], bl4[4][4];
            #pragma unroll
            for (int ntp = 0; ntp < 4; ntp++) {
                int br = ntp * 16 + bx_r;
                int bc = ks * 16 + bx_c;
                ldsm4(bh4[ntp], smem_u32(&KsH[br * ASTR + bc]));
                ldsm4(bl4[ntp], smem_u32(&KsL[br * ASTR + bc]));
            }
            #pragma unroll
            for (int mt = 0; mt < NMT; mt++) {
                uint32_t ah[4], al[4];
                int ar = wr + mt * 16 + (lane & 15);
                int ac = ks * 16 + (lane >> 4) * 8;
                ldsm4(ah, smem_u32(&QsH[ar * ASTR + ac]));
                ldsm4(al, smem_u32(&QsL[ar * ASTR + ac]));
                #pragma unroll
                for (int nt = 0; nt < 8; nt++) {
                    mma_pair(s[mt][nt], ah, bh4[nt >> 1], nt & 1);
                    mma_pair(s[mt][nt], ah, bl4[nt >> 1], nt & 1);
                    mma_pair(s[mt][nt], al, bh4[nt >> 1], nt & 1);
                }
            }
        }

        // ---- scale + mask + online softmax (per mt) ----
        #pragma unroll
        for (int mt = 0; mt < NMT; mt++) {
            const int r0 = q0 + wr + mt * 16 + (lane >> 2);
            float mx0 = -1e30f, mx1 = -1e30f;
            #pragma unroll
            for (int nt = 0; nt < 8; nt++) {
                #pragma unroll
                for (int i = 0; i < 4; i++) s[mt][nt][i] *= 0.125f;
                if (CAUSAL && kt >= ntiles - 2 * NMT) {
                    int col = t0 + nt * 8 + (lane & 3) * 2;
                    if (col     > r0)     s[mt][nt][0] = -1e9f;
                    if (col + 1 > r0)     s[mt][nt][1] = -1e9f;
                    if (col     > r0 + 8) s[mt][nt][2] = -1e9f;
                    if (col + 1 > r0 + 8) s[mt][nt][3] = -1e9f;
                }
                mx0 = fmaxf(mx0, fmaxf(s[mt][nt][0], s[mt][nt][1]));
                mx1 = fmaxf(mx1, fmaxf(s[mt][nt][2], s[mt][nt][3]));
            }
            mx0 = fmaxf(mx0, __shfl_xor_sync(0xffffffffu, mx0, 1));
            mx0 = fmaxf(mx0, __shfl_xor_sync(0xffffffffu, mx0, 2));
            mx1 = fmaxf(mx1, __shfl_xor_sync(0xffffffffu, mx1, 1));
            mx1 = fmaxf(mx1, __shfl_xor_sync(0xffffffffu, mx1, 2));

            float mn0 = fmaxf(m[mt][0], mx0), mn1 = fmaxf(m[mt][1], mx1);
            float al0 = __expf(m[mt][0] - mn0), al1 = __expf(m[mt][1] - mn1);
            float ls0 = 0.f, ls1 = 0.f;
            #pragma unroll
            for (int nt = 0; nt < 8; nt++) {
                s[mt][nt][0] = __expf(s[mt][nt][0] - mn0);
                s[mt][nt][1] = __expf(s[mt][nt][1] - mn0);
                s[mt][nt][2] = __expf(s[mt][nt][2] - mn1);
                s[mt][nt][3] = __expf(s[mt][nt][3] - mn1);
                ls0 += s[mt][nt][0] + s[mt][nt][1];
                ls1 += s[mt][nt][2] + s[mt][nt][3];
            }
            ls0 += __shfl_xor_sync(0xffffffffu, ls0, 1);
            ls0 += __shfl_xor_sync(0xffffffffu, ls0, 2);
            ls1 += __shfl_xor_sync(0xffffffffu, ls1, 1);
            ls1 += __shfl_xor_sync(0xffffffffu, ls1, 2);
            l[mt][0] = l[mt][0] * al0 + ls0;
            l[mt][1] = l[mt][1] * al1 + ls1;
            m[mt][0] = mn0; m[mt][1] = mn1;
            #pragma unroll
            for (int dn = 0; dn < 8; dn++) {
                o[mt][dn][0] *= al0; o[mt][dn][1] *= al0;
                o[mt][dn][2] *= al1; o[mt][dn][3] *= al1;
            }
        }

        // ---- O += P V  (V == K, x4 trans loads shared across mt) ----
        #pragma unroll
        for (int kc = 0; kc < 4; kc++) {
            uint32_t vh4[4][4], vl4[4][4];
            #pragma unroll
            for (int dnp = 0; dnp < 4; dnp++) {
                int vr = kc * 16 + vx_r;
                int vc = dnp * 16 + vx_c;
                ldsm4t(vh4[dnp], smem_u32(&KsH[vr * ASTR + vc]));
                ldsm4t(vl4[dnp], smem_u32(&KsL[vr * ASTR + vc]));
            }
            #pragma unroll
            for (int mt = 0; mt < NMT; mt++) {
                uint32_t pa_h[4], pa_l[4];
                {
                    const float* p0 = s[mt][2 * kc];
                    const float* p1 = s[mt][2 * kc + 1];
                    pa_h[0] = pk2f(p0[0], p0[1]);
                    pa_h[1] = pk2f(p0[2], p0[3]);
                    pa_h[2] = pk2f(p1[0], p1[1]);
                    pa_h[3] = pk2f(p1[2], p1[3]);
                    pa_l[0] = pk2f(p0[0] - __uint_as_float(pa_h[0] << 16),
                                   p0[1] - __uint_as_float(pa_h[0] & 0xFFFF0000u));
                    pa_l[1] = pk2f(p0[2] - __uint_as_float(pa_h[1] << 16),
                                   p0[3] - __uint_as_float(pa_h[1] & 0xFFFF0000u));
                    pa_l[2] = pk2f(p1[0] - __uint_as_float(pa_h[2] << 16),
                                   p1[1] - __uint_as_float(pa_h[2] & 0xFFFF0000u));
                    pa_l[3] = pk2f(p1[2] - __uint_as_float(pa_h[3] << 16),
                                   p1[3] - __uint_as_float(pa_h[3] & 0xFFFF0000u));
                }
                #pragma unroll
                for (int dn = 0; dn < 8; dn++) {
                    mma_pair(o[mt][dn], pa_h, vh4[dn >> 1], dn & 1);
                    mma_pair(o[mt][dn], pa_h, vl4[dn >> 1], dn & 1);
                    mma_pair(o[mt][dn], pa_l, vh4[dn >> 1], dn & 1);
                }
            }
        }
    }

    #pragma unroll
    for (int mt = 0; mt < NMT; mt++) {
        const int r0 = q0 + wr + mt * 16 + (lane >> 2);
        float inv0 = 1.f / l[mt][0], inv1 = 1.f / l[mt][1];
        #pragma unroll
        for (int dn = 0; dn < 8; dn++) {
            int col = h * 64 + dn * 8 + (lane & 3) * 2;
            *(float2*)&Out[(size_t)r0 * D_DIM + col] =
                make_float2(o[mt][dn][0] * inv0, o[mt][dn][1] * inv0);
            *(float2*)&Out[(size_t)(r0 + 8) * D_DIM + col] =
                make_float2(o[mt][dn][2] * inv1, o[mt][dn][3] * inv1);
        }
    }
}

// ---------------- activation fp32 -> bf16 hi/lo split ----------------
__global__ void cvt_act(const float4* __restrict__ x, uint2* __restrict__ hi,
                        uint2* __restrict__ lo, int n4) {
    int i = blockIdx.x * 256 + threadIdx.x;
    if (i >= n4) return;
    float4 v = x[i];
    uint32_t h01 = pk2f(v.x, v.y);
    uint32_t h23 = pk2f(v.z, v.w);
    uint32_t l01 = pk2f(v.x - __uint_as_float(h01 << 16),
                        v.y - __uint_as_float(h01 & 0xFFFF0000u));
    uint32_t l23 = pk2f(v.z - __uint_as_float(h23 << 16),
                        v.w - __uint_as_float(h23 & 0xFFFF0000u));
    hi[i] = make_uint2(h01, h23);
    lo[i] = make_uint2(l01, l23);
}

// ---------------- weight prep ----------------
__global__ void prep_projW(const float* __restrict__ W, bf16* __restrict__ hi,
                           bf16* __restrict__ lo) {
    int idx = blockIdx.x * 256 + threadIdx.x;
    int k = idx & 1023, n = idx >> 10;
    int h = n >> 6, e = n & 63;
    float v = W[(h << 16) + (k << 6) + e];
    bf16 hv = __float2bfloat16(v);
    hi[idx] = hv;
    lo[idx] = __float2bfloat16(v - __bfloat162float(hv));
}

__global__ void prep_T(const float* __restrict__ in, bf16* __restrict__ hi,
                       bf16* __restrict__ lo, int R, int C) {
    __shared__ float t[32][33];
    int bx = blockIdx.x * 32, by = blockIdx.y * 32;
    int tx = threadIdx.x, ty = threadIdx.y;
    #pragma unroll
    for (int i = 0; i < 32; i += 8)
        t[ty + i][tx] = in[(size_t)(by + ty + i) * C + bx + tx];
    __syncthreads();
    #pragma unroll
    for (int i = 0; i < 32; i += 8) {
        float v = t[tx][ty + i];
        bf16 hv = __float2bfloat16(v);
        size_t o = (size_t)(bx + ty + i) * R + by + tx;
        hi[o] = hv;
        lo[o] = __float2bfloat16(v - __bfloat162float(hv));
    }
}

// ---------------- fused residual add + LayerNorm ----------------
__device__ __forceinline__ float warpReduceSum(float v) {
    #pragma unroll
    for (int off = 16; off > 0; off >>= 1)
        v += __shfl_xor_sync(0xffffffffu, v, off);
    return v;
}
__device__ __forceinline__ float blockReduceSum(float v, float* sh) {
    int lane = threadIdx.x & 31, w = threadIdx.x >> 5;
    __syncthreads();
    v = warpReduceSum(v);
    if (lane == 0) sh[w] = v;
    __syncthreads();
    if (w == 0) {
        float t = (lane < 8) ? sh[lane] : 0.f;
        t = warpReduceSum(t);
        if (lane == 0) sh[0] = t;
    }
    __syncthreads();
    return sh[0];
}

template<bool SPLIT>
__global__ void add_ln_kernel(const float* __restrict__ A, const float* __restrict__ Bv,
                              const float* __restrict__ g, const float* __restrict__ beta,
                              float* __restrict__ out,
                              bf16* __restrict__ hi, bf16* __restrict__ lo) {
    __shared__ float red[8];
    const int row = blockIdx.x;
    const int tid = threadIdx.x;
    const int c = tid * 4;
    float4 a4 = *(const float4*)&A [(size_t)row * D_DIM + c];
    float4 b4 = *(const float4*)&Bv[(size_t)row * D_DIM + c];
    float x[4] = { a4.x + b4.x, a4.y + b4.y, a4.z + b4.z, a4.w + b4.w };
    float s = x[0] + x[1] + x[2] + x[3];
    s = blockReduceSum(s, red);
    const float mu = s * (1.f / D_DIM);
    float v = 0.f;
    #pragma unroll
    for (int i = 0; i < 4; i++) { float d = x[i] - mu; v += d * d; }
    v = blockReduceSum(v, red);
    const float rstd = rsqrtf(v * (1.f / D_DIM) + 1e-5f);
    float4 g4 = *(const float4*)&g[c];
    float4 be4 = *(const float4*)&beta[c];
    float r0 = (x[0] - mu) * rstd * g4.x + be4.x;
    float r1 = (x[1] - mu) * rstd * g4.y + be4.y;
    float r2 = (x[2] - mu) * rstd * g4.z + be4.z;
    float r3 = (x[3] - mu) * rstd * g4.w + be4.w;
    *(float4*)&out[(size_t)row * D_DIM + c] = make_float4(r0, r1, r2, r3);
    if (SPLIT) {
        uint32_t h01 = pk2f(r0, r1);
        uint32_t h23 = pk2f(r2, r3);
        uint32_t l01 = pk2f(r0 - __uint_as_float(h01 << 16),
                            r1 - __uint_as_float(h01 & 0xFFFF0000u));
        uint32_t l23 = pk2f(r2 - __uint_as_float(h23 << 16),
                            r3 - __uint_as_float(h23 & 0xFFFF0000u));
        *(uint2*)&hi[(size_t)row * D_DIM + c] = make_uint2(h01, h23);
        *(uint2*)&lo[(size_t)row * D_DIM + c] = make_uint2(l01, l23);
    }
}

// ---------------- launch ----------------
extern "C" void kernel_launch(void* const* d_in, const int* in_sizes, int n_in,
                              void* d_out, int out_size) {
    const float* y   = (const float*)d_in[0];
    const float* enc = (const float*)d_in[1];
    const float* WqS = (const float*)d_in[2];
    const float* bqS = (const float*)d_in[3];
    const float* WqC = (const float*)d_in[4];
    const float* bqC = (const float*)d_in[5];
    const float* g1  = (const float*)d_in[6];
    const float* be1 = (const float*)d_in[7];
    const float* g2  = (const float*)d_in[8];
    const float* be2 = (const float*)d_in[9];
    const float* g3  = (const float*)d_in[10];
    const float* be3 = (const float*)d_in[11];
    const float* w1  = (const float*)d_in[12];
    const float* b1  = (const float*)d_in[13];
    const float* w2  = (const float*)d_in[14];
    const float* b2  = (const float*)d_in[15];
    float* outp = (float*)d_out;

    float *AO, *y1, *y2, *FF;
    bf16 *Phi, *Plo, *CatHi, *CatLo, *QKhi, *QKlo, *Hhi, *Hlo, *Ahi, *Alo;
    bf16 *BtS_hi, *BtS_lo, *BtC_hi, *BtC_lo, *Bt1_hi, *Bt1_lo, *Bt2_hi, *Bt2_lo;
    cudaGetSymbolAddress((void**)&AO, g_AO);
    cudaGetSymbolAddress((void**)&y1, g_y1);
    cudaGetSymbolAddress((void**)&y2, g_y2);
    cudaGetSymbolAddress((void**)&FF, g_FF);
    cudaGetSymbolAddress((void**)&Phi,   g_Phi);
    cudaGetSymbolAddress((void**)&Plo,   g_Plo);
    cudaGetSymbolAddress((void**)&CatHi, g_Cat_hi);
    cudaGetSymbolAddress((void**)&CatLo, g_Cat_lo);
    cudaGetSymbolAddress((void**)&QKhi,  g_QK_hi);
    cudaGetSymbolAddress((void**)&QKlo,  g_QK_lo);
    cudaGetSymbolAddress((void**)&Hhi,   g_Hhi);
    cudaGetSymbolAddress((void**)&Hlo,   g_Hlo);
    cudaGetSymbolAddress((void**)&Ahi,   g_Ahi);
    cudaGetSymbolAddress((void**)&Alo,   g_Alo);
    cudaGetSymbolAddress((void**)&BtS_hi, g_BtS_hi);
    cudaGetSymbolAddress((void**)&BtS_lo, g_BtS_lo);
    cudaGetSymbolAddress((void**)&BtC_hi, g_BtC_hi);
    cudaGetSymbolAddress((void**)&BtC_lo, g_BtC_lo);
    cudaGetSymbolAddress((void**)&Bt1_hi, g_Bt1_hi);
    cudaGetSymbolAddress((void**)&Bt1_lo, g_Bt1_lo);
    cudaGetSymbolAddress((void**)&Bt2_hi, g_Bt2_hi);
    cudaGetSymbolAddress((void**)&Bt2_lo, g_Bt2_lo);

    const int GEMM_SMEM = 3 * 4 * GSTG * 2;                        // 122880 B
    const int ATT_SMEM1 = (2 * 128 * ASTR + 6 * KELT) * 2;         // 92160 B
    const int ATT_SMEM2 = (2 * 256 * ASTR + 6 * KELT) * 2;         // 129024 B
    cudaFuncSetAttribute(mm_gemm<false, true>,  cudaFuncAttributeMaxDynamicSharedMemorySize, GEMM_SMEM);
    cudaFuncSetAttribute(mm_gemm<true, true>,   cudaFuncAttributeMaxDynamicSharedMemorySize, GEMM_SMEM);
    cudaFuncSetAttribute(mm_gemm<false, false>, cudaFuncAttributeMaxDynamicSharedMemorySize, GEMM_SMEM);
    cudaFuncSetAttribute(mm_attn<true, 1>,  cudaFuncAttributeMaxDynamicSharedMemorySize, ATT_SMEM1);
    cudaFuncSetAttribute(mm_attn<false, 2>, cudaFuncAttributeMaxDynamicSharedMemorySize, ATT_SMEM2);

    // weight prep
    prep_projW<<<(D_DIM * D_DIM) / 256, 256>>>(WqS, BtS_hi, BtS_lo);
    prep_projW<<<(D_DIM * D_DIM) / 256, 256>>>(WqC, BtC_hi, BtC_lo);
    prep_T<<<dim3(HID_DIM / 32, D_DIM / 32), dim3(32, 8)>>>(w1, Bt1_hi, Bt1_lo, D_DIM, HID_DIM);
    prep_T<<<dim3(D_DIM / 32, HID_DIM / 32), dim3(32, 8)>>>(w2, Bt2_hi, Bt2_lo, HID_DIM, D_DIM);

    const int N_SD = S_LEN * D_DIM;

    // convert inputs: y -> A, enc -> Cat second half
    cvt_act<<<N_SD / 4 / 256, 256>>>((const float4*)y, (uint2*)Ahi, (uint2*)Alo, N_SD / 4);
    cvt_act<<<N_SD / 4 / 256, 256>>>((const float4*)enc,
        (uint2*)(CatHi + N_SD), (uint2*)(CatLo + N_SD), N_SD / 4);

    // P (hi/lo) = y @ WtS + bqS
    mm_gemm<false, true><<<dim3(D_DIM / 128, S_LEN / 128), 256, GEMM_SMEM>>>(
        Ahi, Alo, BtS_hi, BtS_lo, bqS, nullptr, Phi, Plo, D_DIM, D_DIM);

    // self attention (q=k=v=P), causal — flattened LPT grid, 128-row tiles
    mm_attn<true, 1><<<dim3((S_LEN / 128) * H_HEADS), 256, ATT_SMEM1>>>(Phi, Plo, Phi, Plo, AO);
    // y1 = LN(y + AO), also split into Cat first half
    add_ln_kernel<true><<<S_LEN, 256>>>(y, AO, g1, be1, y1, CatHi, CatLo);

    // [Qc ; Kc] = [y1 ; enc] @ WtC + bqC   (one combined GEMM, M = 4096)
    mm_gemm<false, true><<<dim3(D_DIM / 128, 2 * S_LEN / 128), 256, GEMM_SMEM>>>(
        CatHi, CatLo, BtC_hi, BtC_lo, bqC, nullptr, QKhi, QKlo, D_DIM, D_DIM);

    // cross attention (k=v), non-causal — 256-row tiles, 128 CTAs = 1 wave
    mm_attn<false, 2><<<dim3(S_LEN / 256, H_HEADS), 256, ATT_SMEM2>>>(
        QKhi, QKlo, QKhi + N_SD, QKlo + N_SD, AO);
    // y2 = LN(y1 + AO), split into A
    add_ln_kernel<true><<<S_LEN, 256>>>(y1, AO, g2, be2, y2, Ahi, Alo);

    // Hd (hi/lo) = relu(y2 @ w1 + b1)
    mm_gemm<true, true><<<dim3(HID_DIM / 128, S_LEN / 128), 256, GEMM_SMEM>>>(
        Ahi, Alo, Bt1_hi, Bt1_lo, b1, nullptr, Hhi, Hlo, HID_DIM, D_DIM);

    // FF = Hd @ w2 + b2 (fp32)
    mm_gemm<false, false><<<dim3(D_DIM / 128, S_LEN / 128), 256, GEMM_SMEM>>>(
        Hhi, Hlo, Bt2_hi, Bt2_lo, b2, FF, nullptr, nullptr, D_DIM, HID_DIM);

    // out = LN(y2 + FF)
    add_ln_kernel<false><<<S_LEN, 256>>>(y2, FF, g3, be3, outp, nullptr, nullptr);
}